// round 11
// baseline (speedup 1.0000x reference)
#include <cuda_runtime.h>
#include <cuda_bf16.h>
#include <math.h>

#define S_  64
#define E_  16
#define B_  32
#define D_  1024
#define H_  16
#define SB_ (S_*B_)

typedef unsigned long long u64;
typedef unsigned int u32;
typedef __nv_bfloat16 bf16;

// ---------------- device scratch ----------------
__device__ float g_qp [D_];
__device__ float g_qk [H_*D_];
__device__ float g_bcv[D_];
__device__ int   g_flags[68];        // [0]=wcv, [1+mb]=y (32), [33+mb]=ctx (32)
__device__ bf16 g_yhi[SB_*H_*D_];
__device__ bf16 g_ylo[SB_*H_*D_];
__device__ bf16 g_wvi_hi[D_*D_], g_wvi_lo[D_*D_];
__device__ bf16 g_wvl_hi[D_*D_], g_wvl_lo[D_*D_];
__device__ bf16 g_wcv_hi[D_*D_], g_wcv_lo[D_*D_];
__device__ bf16 g_wo_hi [D_*D_], g_wo_lo [D_*D_];
__device__ bf16 g_ctx_hi[SB_*D_], g_ctx_lo[SB_*D_];

// ---------------- helpers ----------------
__device__ __forceinline__ u32 smem_u32(const void* p) {
    u32 a; asm("{ .reg .u64 t; cvta.to.shared.u64 t, %1; cvt.u32.u64 %0, t; }"
               : "=r"(a) : "l"(p)); return a;
}
#define CPA(dst, src) \
    asm volatile("cp.async.cg.shared.global [%0], [%1], 16;" :: "r"(dst), "l"(src))
#define CPC() asm volatile("cp.async.commit_group;" ::: "memory")
#define CPW(n) asm volatile("cp.async.wait_group %0;" :: "n"(n) : "memory")

__device__ __forceinline__ void store_split(bf16* hi, bf16* lo, long idx,
                                            float v0, float v1) {
    bf16 h0 = __float2bfloat16_rn(v0), h1 = __float2bfloat16_rn(v1);
    bf16 l0 = __float2bfloat16_rn(v0 - __bfloat162float(h0));
    bf16 l1 = __float2bfloat16_rn(v1 - __bfloat162float(h1));
    *(u32*)&hi[idx] = (u32)__bfloat16_as_ushort(h0) | ((u32)__bfloat16_as_ushort(h1) << 16);
    *(u32*)&lo[idx] = (u32)__bfloat16_as_ushort(l0) | ((u32)__bfloat16_as_ushort(l1) << 16);
}

// producer signal: all writes done -> fence -> count
__device__ __forceinline__ void sig_flag(int* f) {
    __threadfence();
    __syncthreads();
    if (threadIdx.x == 0) atomicAdd(f, 1);
}
// consumer wait
__device__ __forceinline__ void wait_flag(int* f, int target) {
    if (threadIdx.x == 0) {
        while (atomicAdd(f, 0) < target) __nanosleep(128);
        __threadfence();
    }
    __syncthreads();
}

// ================= front-end kernel 1: splits | bcv | qp =================
__device__ __forceinline__
void rowdot_warp(const float* __restrict__ W, const float* __restrict__ v,
                 const float* __restrict__ bias, float* __restrict__ out,
                 int w, int lane, float scale)
{
    const float4* row4 = (const float4*)(W + (long)w * D_);
    const float4* v4   = (const float4*)v;
    float acc = 0.f;
    #pragma unroll 8
    for (int c = lane; c < D_/4; c += 32) {
        float4 a = row4[c], b = v4[c];
        acc += a.x*b.x + a.y*b.y + a.z*b.z + a.w*b.w;
    }
    #pragma unroll
    for (int o = 16; o; o >>= 1) acc += __shfl_xor_sync(0xffffffffu, acc, o);
    if (!lane) out[w] = (acc + bias[w]) * scale;
}

__global__ __launch_bounds__(256)
void k_front(const float* __restrict__ Wo, const float* __restrict__ Wv_in,
             const float* __restrict__ Wv_lin,
             const float* __restrict__ bv_lin, const float* __restrict__ bv_in,
             const float* __restrict__ Wq_in, const float* __restrict__ query,
             const float* __restrict__ bq_in)
{
    const int blk = blockIdx.x, t = threadIdx.x;
    if (blk < 1536) {
        int m = blk >> 9;
        int off = (blk & 511) * 1024;
        const float* W = (m == 0) ? Wo : (m == 1) ? Wv_in : Wv_lin;
        bf16* hi = (m == 0) ? g_wo_hi : (m == 1) ? g_wvi_hi : g_wvl_hi;
        bf16* lo = (m == 0) ? g_wo_lo : (m == 1) ? g_wvi_lo : g_wvl_lo;
        #pragma unroll
        for (int i = 0; i < 4; i++) {
            int idx = off + i * 256 + t;
            float2 v = ((const float2*)W)[idx];
            bf16 hx = __float2bfloat16_rn(v.x), hy = __float2bfloat16_rn(v.y);
            bf16 lx = __float2bfloat16_rn(v.x - __bfloat162float(hx));
            bf16 ly = __float2bfloat16_rn(v.y - __bfloat162float(hy));
            ((u32*)hi)[idx] = (u32)__bfloat16_as_ushort(hx) | ((u32)__bfloat16_as_ushort(hy) << 16);
            ((u32*)lo)[idx] = (u32)__bfloat16_as_ushort(lx) | ((u32)__bfloat16_as_ushort(ly) << 16);
        }
    } else if (blk < 1664) {
        rowdot_warp(Wv_in, bv_lin, bv_in, g_bcv,
                    (blk - 1536) * 8 + (t >> 5), t & 31, 1.0f);
    } else {
        rowdot_warp(Wq_in, query, bq_in, g_qp,
                    (blk - 1664) * 8 + (t >> 5), t & 31, 0.125f);
    }
}

// ================= front-end kernel 2: t-chunk + qk (split-K atomics) =====
__global__ __launch_bounds__(128)
void k_tqk(const float* __restrict__ Wk_in, const float* __restrict__ Wk_lin)
{
    __shared__ float ts[1024];     // [16 h][64 mm]
    const int t  = threadIdx.x;
    const int d  = blockIdx.x * 128 + t;
    const int m0 = blockIdx.y * 64;
    #pragma unroll
    for (int i = 0; i < 8; i++) {
        int idx = i * 128 + t;
        int h = idx >> 6, mm = idx & 63;
        float a = 0.f;
        #pragma unroll 8
        for (int j = 0; j < 64; j++)
            a += g_qp[h*64 + j] * Wk_in[(long)(h*64 + j) * D_ + m0 + mm];
        ts[idx] = a;
    }
    __syncthreads();
    float acc[16];
    #pragma unroll
    for (int h = 0; h < 16; h++) acc[h] = 0.f;
    for (int m = 0; m < 64; m++) {
        float w = Wk_lin[(long)(m0 + m) * D_ + d];
        #pragma unroll
        for (int h = 0; h < 16; h++) acc[h] += ts[h*64 + m] * w;
    }
    #pragma unroll
    for (int h = 0; h < 16; h++) atomicAdd(&g_qk[h*D_ + d], acc[h]);
}

// ================= GEMM machinery =================
// 64 chunks of K=32. hi phase (c<32): A=Ahi vs Bhi+Blo; lo phase: A=Alo vs Bhi.
#define LS 40
#define NCHN 64

// ---- BM=128 BN=128 BTRANS, 256 threads (Wcv) ----
__device__ __forceinline__
void load_tile_wcv(bf16* As, bf16* Bs, int c, int bm, int bn, int t)
{
    const bool hip = c < 32;
    const int kb = (c & 31) * 32;
    const bf16* Ap = hip ? g_wvi_hi : g_wvi_lo;
    {
        int row = t >> 1, ch = (t & 1) * 2;
        const bf16* src = Ap + (long)(bm + row) * D_ + kb + ch * 8;
        u32 dst = smem_u32(&As[row*LS + ch*8]);
        CPA(dst, src); CPA(dst + 16, src + 8);
    }
    // B = Wv_lin [m][n], transpose to smem [n][m]
    int mrow = t >> 3, nc0 = (t & 7) * 16;
    {
        const bf16* s0 = g_wvl_hi + (long)(kb + mrow) * D_ + bn + nc0;
        bf16 tmp[16];
        *(uint4*)tmp = *(const uint4*)s0;
        *(uint4*)(tmp + 8) = *(const uint4*)(s0 + 8);
        #pragma unroll
        for (int j = 0; j < 16; j++) Bs[(nc0 + j)*LS + mrow] = tmp[j];
    }
    if (hip) {
        const bf16* s1 = g_wvl_lo + (long)(kb + mrow) * D_ + bn + nc0;
        bf16 tmp[16];
        *(uint4*)tmp = *(const uint4*)s1;
        *(uint4*)(tmp + 8) = *(const uint4*)(s1 + 8);
        #pragma unroll
        for (int j = 0; j < 16; j++) Bs[128*LS + (nc0 + j)*LS + mrow] = tmp[j];
    }
}

__device__ __forceinline__
void mma_part_wcv(const bf16* Bp, const u32 (&a)[2][4], float (&acc)[2][8][4],
                  int kk, int lane, int wn)
{
    #pragma unroll
    for (int nt = 0; nt < 8; nt++) {
        int l = lane & 15;
        u32 bd = smem_u32(&Bp[(wn*64 + nt*8 + (l & 7))*LS + kk + ((l >> 3) << 3)]);
        u32 b0, b1;
        asm volatile("ldmatrix.sync.aligned.m8n8.x2.shared.b16 {%0,%1}, [%2];"
            : "=r"(b0), "=r"(b1) : "r"(bd));
        #pragma unroll
        for (int mt = 0; mt < 2; mt++) {
            asm volatile(
                "mma.sync.aligned.m16n8k16.row.col.f32.bf16.bf16.f32 "
                "{%0,%1,%2,%3}, {%4,%5,%6,%7}, {%8,%9}, {%0,%1,%2,%3};"
                : "+f"(acc[mt][nt][0]), "+f"(acc[mt][nt][1]),
                  "+f"(acc[mt][nt][2]), "+f"(acc[mt][nt][3])
                : "r"(a[mt][0]), "r"(a[mt][1]), "r"(a[mt][2]), "r"(a[mt][3]),
                  "r"(b0), "r"(b1));
        }
    }
}

__device__ void wcv_body(char* smem, int bm, int bn)
{
    bf16* Asg = (bf16*)smem;
    bf16* Bsg = (bf16*)smem + 2 * 128 * LS;
    const int t = threadIdx.x;
    float acc[2][8][4];
    #pragma unroll
    for (int i = 0; i < 2; i++)
        #pragma unroll
        for (int j = 0; j < 8; j++)
            #pragma unroll
            for (int q = 0; q < 4; q++) acc[i][j][q] = 0.f;

    load_tile_wcv(Asg, Bsg, 0, bm, bn, t);
    CPC();
    int lane = t & 31, wid = t >> 5;
    int wm = wid & 3, wn = wid >> 2;
    for (int c = 0; c < NCHN; c++) {
        int st = c & 1;
        CPW(0);
        __syncthreads();
        if (c + 1 < NCHN) {
            load_tile_wcv(Asg + (st^1)*128*LS, Bsg + (st^1)*2*128*LS, c + 1,
                          bm, bn, t);
            CPC();
        }
        const bf16* As = Asg + st*128*LS;
        const bf16* Bs = Bsg + st*2*128*LS;
        bool hip = c < 32;
        #pragma unroll
        for (int kk = 0; kk < 32; kk += 16) {
            u32 a[2][4];
            #pragma unroll
            for (int mt = 0; mt < 2; mt++) {
                u32 ad = smem_u32(&As[(wm*32 + mt*16 + (lane & 15))*LS + kk + ((lane >> 4) << 3)]);
                asm volatile("ldmatrix.sync.aligned.m8n8.x4.shared.b16 {%0,%1,%2,%3}, [%4];"
                    : "=r"(a[mt][0]), "=r"(a[mt][1]), "=r"(a[mt][2]), "=r"(a[mt][3]) : "r"(ad));
            }
            mma_part_wcv(Bs, a, acc, kk, lane, wn);
            if (hip) mma_part_wcv(Bs + 128*LS, a, acc, kk, lane, wn);
        }
    }

    int gr = lane >> 2, gc = (lane & 3) * 2;
    #pragma unroll
    for (int mt = 0; mt < 2; mt++) {
        #pragma unroll
        for (int nt = 0; nt < 8; nt++) {
            int col = bn + wn*64 + nt*8 + gc;
            long r0 = bm + wm*32 + mt*16 + gr;
            long r1 = r0 + 8;
            store_split(g_wcv_hi, g_wcv_lo, r0*D_ + col, acc[mt][nt][0], acc[mt][nt][1]);
            store_split(g_wcv_hi, g_wcv_lo, r1*D_ + col, acc[mt][nt][2], acc[mt][nt][3]);
        }
    }
}

// ---- BM=64 BN=64, 256 threads (ctx + out) ----
__device__ void mma64_body(char* smem,
    const bf16* __restrict__ Ah, const bf16* __restrict__ Al, int lda,
    const bf16* __restrict__ Bh, const bf16* __restrict__ Bl, int ldb,
    float* __restrict__ Cf, bf16* __restrict__ Chi, bf16* __restrict__ Clo,
    long coff, const float* __restrict__ bi, int bm, int bn)
{
    bf16* Asg = (bf16*)smem;                  // 2 stages x 64xLS
    bf16* Bsg = (bf16*)smem + 2 * 64 * LS;    // 2 stages x 2x64xLS
    const int t = threadIdx.x;
    const int lrow = t >> 2, lch = t & 3;
    float acc[2][2][4];
    #pragma unroll
    for (int i = 0; i < 2; i++)
        #pragma unroll
        for (int j = 0; j < 2; j++)
            #pragma unroll
            for (int q = 0; q < 4; q++) acc[i][j][q] = 0.f;

#define LOAD64(As, Bs, c) do { \
        bool hip_ = (c) < 32; int kb_ = ((c) & 31) * 32; \
        const bf16* Ap_ = hip_ ? Ah : Al; \
        CPA(smem_u32(&(As)[lrow*LS + lch*8]), Ap_ + (long)(bm + lrow)*lda + kb_ + lch*8); \
        CPA(smem_u32(&(Bs)[lrow*LS + lch*8]), Bh + (long)(bn + lrow)*ldb + kb_ + lch*8); \
        if (hip_) CPA(smem_u32(&(Bs)[64*LS + lrow*LS + lch*8]), \
                      Bl + (long)(bn + lrow)*ldb + kb_ + lch*8); \
    } while (0)

    LOAD64(Asg, Bsg, 0); CPC();
    int lane = t & 31, wid = t >> 5;
    int wm = wid & 1, wn = wid >> 1;          // 2 x 4 warp grid
    for (int c = 0; c < NCHN; c++) {
        int st = c & 1;
        CPW(0);
        __syncthreads();
        if (c + 1 < NCHN) {
            LOAD64(Asg + (st^1)*64*LS, Bsg + (st^1)*2*64*LS, c + 1);
            CPC();
        }
        const bf16* As = Asg + st*64*LS;
        const bf16* Bs = Bsg + st*2*64*LS;
        bool hip = c < 32;
        #pragma unroll
        for (int kk = 0; kk < 32; kk += 16) {
            u32 a[2][4];
            #pragma unroll
            for (int mt = 0; mt < 2; mt++) {
                u32 ad = smem_u32(&As[(wm*32 + mt*16 + (lane & 15))*LS + kk + ((lane >> 4) << 3)]);
                asm volatile("ldmatrix.sync.aligned.m8n8.x4.shared.b16 {%0,%1,%2,%3}, [%4];"
                    : "=r"(a[mt][0]), "=r"(a[mt][1]), "=r"(a[mt][2]), "=r"(a[mt][3]) : "r"(ad));
            }
            #pragma unroll
            for (int pass = 0; pass < 2; pass++) {
                if (pass == 1 && !hip) break;
                const bf16* Bp = Bs + pass * 64 * LS;
                #pragma unroll
                for (int nt = 0; nt < 2; nt++) {
                    int l = lane & 15;
                    u32 bd = smem_u32(&Bp[(wn*16 + nt*8 + (l & 7))*LS + kk + ((l >> 3) << 3)]);
                    u32 b0, b1;
                    asm volatile("ldmatrix.sync.aligned.m8n8.x2.shared.b16 {%0,%1}, [%2];"
                        : "=r"(b0), "=r"(b1) : "r"(bd));
                    #pragma unroll
                    for (int mt = 0; mt < 2; mt++) {
                        asm volatile(
                            "mma.sync.aligned.m16n8k16.row.col.f32.bf16.bf16.f32 "
                            "{%0,%1,%2,%3}, {%4,%5,%6,%7}, {%8,%9}, {%0,%1,%2,%3};"
                            : "+f"(acc[mt][nt][0]), "+f"(acc[mt][nt][1]),
                              "+f"(acc[mt][nt][2]), "+f"(acc[mt][nt][3])
                            : "r"(a[mt][0]), "r"(a[mt][1]), "r"(a[mt][2]), "r"(a[mt][3]),
                              "r"(b0), "r"(b1));
                    }
                }
            }
        }
    }
#undef LOAD64

    int gr = lane >> 2, gc = (lane & 3) * 2;
    #pragma unroll
    for (int mt = 0; mt < 2; mt++) {
        #pragma unroll
        for (int nt = 0; nt < 2; nt++) {
            int colL = wn*16 + nt*8 + gc;
            long ccol = coff + bn + colL;
            float b0 = bi[bn + colL], b1 = bi[bn + colL + 1];
            long r0 = bm + wm*32 + mt*16 + gr;
            long r1 = r0 + 8;
            float v00 = acc[mt][nt][0] + b0, v01 = acc[mt][nt][1] + b1;
            float v10 = acc[mt][nt][2] + b0, v11 = acc[mt][nt][3] + b1;
            if (Cf) {
                *(float2*)&Cf[r0*1024 + ccol] = make_float2(v00, v01);
                *(float2*)&Cf[r1*1024 + ccol] = make_float2(v10, v11);
            } else {
                store_split(Chi, Clo, r0*1024 + ccol, v00, v01);
                store_split(Chi, Clo, r1*1024 + ccol, v10, v11);
            }
        }
    }
}

// ================= fused scores + softmax + y =================
#define PX 1028
__device__ __forceinline__ void aggr_body(float* sm, const float* __restrict__ x, int sb)
{
    float* xs  = sm;
    float* att = sm + 16 * PX;

    const int t = threadIdx.x;
    const int s = sb >> 5, b = sb & 31;

    #pragma unroll
    for (int i = 0; i < 16; i++) {
        int f4 = i * 256 + t;
        int e = f4 >> 8, d4 = f4 & 255;
        float4 v = ((const float4*)x)[((long)((s*16 + e)*32 + b)) * 256 + d4];
        *(float4*)&xs[e*PX + d4*4] = v;
    }
    __syncthreads();

    {
        const int h = t >> 4, e = t & 15;
        const float4* xr = (const float4*)&xs[e*PX];
        const float4* qr = (const float4*)&g_qk[h*D_];
        float acc = 0.f;
        #pragma unroll 8
        for (int i = 0; i < 256; i++) {
            float4 a = xr[i], q = qr[i];
            acc += a.x*q.x + a.y*q.y + a.z*q.z + a.w*q.w;
        }
        float mx = acc;
        #pragma unroll
        for (int o = 8; o; o >>= 1) mx = fmaxf(mx, __shfl_xor_sync(0xffffffffu, mx, o, 16));
        float p = __expf(acc - mx);
        float sum = p;
        #pragma unroll
        for (int o = 8; o; o >>= 1) sum += __shfl_xor_sync(0xffffffffu, sum, o, 16);
        att[t] = p / sum;
    }
    __syncthreads();

    float4 acch[16];
    #pragma unroll
    for (int h = 0; h < 16; h++) acch[h] = make_float4(0.f, 0.f, 0.f, 0.f);
    #pragma unroll
    for (int et = 0; et < 4; et++) {
        float4 xv[4];
        #pragma unroll
        for (int e2 = 0; e2 < 4; e2++)
            xv[e2] = *(const float4*)&xs[(et*4 + e2)*PX + t*4];
        #pragma unroll
        for (int h = 0; h < 16; h++) {
            #pragma unroll
            for (int e2 = 0; e2 < 4; e2++) {
                float a = att[h*16 + et*4 + e2];
                acch[h].x = fmaf(a, xv[e2].x, acch[h].x);
                acch[h].y = fmaf(a, xv[e2].y, acch[h].y);
                acch[h].z = fmaf(a, xv[e2].z, acch[h].z);
                acch[h].w = fmaf(a, xv[e2].w, acch[h].w);
            }
        }
    }
    #pragma unroll
    for (int h = 0; h < 16; h++) {
        float4 v = acch[h];
        long base = ((long)sb*16 + h)*1024 + t*4;
        store_split(g_yhi, g_ylo, base,     v.x, v.y);
        store_split(g_yhi, g_ylo, base + 2, v.z, v.w);
    }
}

// ================= MEGA kernel: Wcv | aggr | ctx | out, flag-pipelined ====
// bids: [0,64) Wcv ; [64,2112) aggr ; [2112,2624) ctx ; [2624,3136) out
__global__ __launch_bounds__(256)
void k_mega(const float* __restrict__ x, float* __restrict__ out,
            const float* __restrict__ bo)
{
    extern __shared__ char sm[];
    const int bid = blockIdx.x;
    if (bid < 64) {
        wcv_body(sm, (bid >> 3) * 128, (bid & 7) * 128);
        sig_flag(&g_flags[0]);
    } else if (bid < 64 + SB_) {
        int sb = bid - 64;
        aggr_body((float*)sm, x, sb);
        sig_flag(&g_flags[1 + (sb >> 6)]);
    } else if (bid < 64 + SB_ + 512) {
        int idx = bid - (64 + SB_);
        int mb = idx >> 4, h = idx & 15;     // mb-major: earliest-ready first
        wait_flag(&g_flags[0], 64);
        wait_flag(&g_flags[1 + mb], 64);
        mma64_body(sm,
                   g_yhi + h*D_, g_ylo + h*D_, H_*D_,
                   g_wcv_hi + (long)h*64*D_, g_wcv_lo + (long)h*64*D_, D_,
                   (float*)0, g_ctx_hi, g_ctx_lo, (long)h*64,
                   g_bcv + h*64, mb*64, 0);
        sig_flag(&g_flags[33 + mb]);
    } else {
        int idx = bid - (64 + SB_ + 512);
        int mb = idx >> 4, nb = idx & 15;
        wait_flag(&g_flags[33 + mb], 16);
        mma64_body(sm,
                   g_ctx_hi, g_ctx_lo, D_,
                   g_wo_hi, g_wo_lo, D_,
                   out, (bf16*)0, (bf16*)0, 0,
                   bo, mb*64, nb*64);
    }
}

// ================= launch =================
extern "C" void kernel_launch(void* const* d_in, const int* in_sizes, int n_in,
                              void* d_out, int out_size)
{
    const float* x = (const float*)d_in[0];
    int qi = n_in - 13;
    const float* query  = (const float*)d_in[qi + 0];
    const float* Wk_lin = (const float*)d_in[qi + 1];
    const float* Wv_lin = (const float*)d_in[qi + 3];
    const float* bv_lin = (const float*)d_in[qi + 4];
    const float* Wq_in  = (const float*)d_in[qi + 5];
    const float* bq_in  = (const float*)d_in[qi + 6];
    const float* Wk_in  = (const float*)d_in[qi + 7];
    const float* Wv_in  = (const float*)d_in[qi + 9];
    const float* bv_in  = (const float*)d_in[qi + 10];
    const float* Wo     = (const float*)d_in[qi + 11];
    const float* bo     = (const float*)d_in[qi + 12];
    float* out = (float*)d_out;

    float* p_qk; int* p_flags;
    cudaGetSymbolAddress((void**)&p_qk,    g_qk);
    cudaGetSymbolAddress((void**)&p_flags, g_flags);

    const int MEGA_SMEM = (16*PX + 256) * 4;   // 66816 >= wcv body 61440
    static int attr_set = 0;
    if (!attr_set) {
        cudaFuncSetAttribute(k_mega, cudaFuncAttributeMaxDynamicSharedMemorySize,
                             MEGA_SMEM);
        attr_set = 1;
    }

    // 0. zero qk accumulator + pipeline flags (must reset every replay)
    cudaMemsetAsync(p_qk, 0, H_*D_*sizeof(float), 0);
    cudaMemsetAsync(p_flags, 0, 68*sizeof(int), 0);
    // 1. front: weight splits | bcv | qp   (1792 near-uniform blocks)
    k_front<<<1792, 256>>>(Wo, Wv_in, Wv_lin, bv_lin, bv_in, Wq_in, query, bq_in);
    // 2. qk = fold(qp, Wk_in, Wk_lin)   (t-chunk recomputed in smem)
    k_tqk<<<dim3(8, 16), 128>>>(Wk_in, Wk_lin);
    // 3. MEGA: Wcv || aggr -> ctx -> out, pipelined via flags
    k_mega<<<64 + SB_ + 512 + 512, 256, MEGA_SMEM>>>(x, out, bo);
}

// round 14
// speedup vs baseline: 1.6202x; 1.6202x over previous
#include <cuda_runtime.h>
#include <cuda_bf16.h>
#include <math.h>

#define S_  64
#define E_  16
#define B_  32
#define D_  1024
#define H_  16
#define SB_ (S_*B_)

typedef unsigned long long u64;
typedef unsigned int u32;
typedef __nv_bfloat16 bf16;

// ---------------- device scratch (R8 layout) ----------------
__device__ float g_qp [D_];
__device__ float g_t  [H_*D_];
__device__ float g_qk [H_*D_];
__device__ float g_bcv[D_];
__device__ bf16 g_yhi[SB_*H_*D_];
__device__ bf16 g_ylo[SB_*H_*D_];
__device__ bf16 g_wvi_hi[D_*D_], g_wvi_lo[D_*D_];
__device__ bf16 g_wvl_hi[D_*D_], g_wvl_lo[D_*D_];
__device__ bf16 g_wcv_hi[D_*D_], g_wcv_lo[D_*D_];
__device__ bf16 g_wo_hi [D_*D_], g_wo_lo [D_*D_];
__device__ bf16 g_ctx_hi[SB_*D_], g_ctx_lo[SB_*D_];

// ---------------- helpers ----------------
__device__ __forceinline__ u32 smem_u32(const void* p) {
    u32 a; asm("{ .reg .u64 t; cvta.to.shared.u64 t, %1; cvt.u32.u64 %0, t; }"
               : "=r"(a) : "l"(p)); return a;
}
#define CPA(dst, src) \
    asm volatile("cp.async.cg.shared.global [%0], [%1], 16;" :: "r"(dst), "l"(src))
#define CPC() asm volatile("cp.async.commit_group;" ::: "memory")
#define CPW(n) asm volatile("cp.async.wait_group %0;" :: "n"(n) : "memory")

__device__ __forceinline__ void store_split(bf16* hi, bf16* lo, long idx,
                                            float v0, float v1) {
    bf16 h0 = __float2bfloat16_rn(v0), h1 = __float2bfloat16_rn(v1);
    bf16 l0 = __float2bfloat16_rn(v0 - __bfloat162float(h0));
    bf16 l1 = __float2bfloat16_rn(v1 - __bfloat162float(h1));
    *(u32*)&hi[idx] = (u32)__bfloat16_as_ushort(h0) | ((u32)__bfloat16_as_ushort(h1) << 16);
    *(u32*)&lo[idx] = (u32)__bfloat16_as_ushort(l0) | ((u32)__bfloat16_as_ushort(l1) << 16);
}

// ================= R8 front-end (float4 rowdot from passing R10) ==========
__global__ void k_rowdot(const float* __restrict__ W, const float* __restrict__ v,
                         const float* __restrict__ bias, float* __restrict__ out,
                         int rows, int cols, float scale)
{
    int w = (blockIdx.x * blockDim.x + threadIdx.x) >> 5;
    int lane = threadIdx.x & 31;
    if (w >= rows) return;
    const float4* row4 = (const float4*)(W + (long)w * cols);
    const float4* v4   = (const float4*)v;
    float acc = 0.f;
    #pragma unroll 8
    for (int c = lane; c < cols/4; c += 32) {
        float4 a = row4[c], b = v4[c];
        acc += a.x*b.x + a.y*b.y + a.z*b.z + a.w*b.w;
    }
    #pragma unroll
    for (int o = 16; o; o >>= 1) acc += __shfl_xor_sync(0xffffffffu, acc, o);
    if (!lane) out[w] = (acc + bias[w]) * scale;
}

__global__ void k_t(const float* __restrict__ Wk_in)
{
    int h = blockIdx.y;
    int m = blockIdx.x * 256 + threadIdx.x;
    float acc = 0.f;
    #pragma unroll 8
    for (int j = 0; j < 64; j++)
        acc += g_qp[h*64 + j] * Wk_in[(long)(h*64 + j) * D_ + m];
    g_t[h*D_ + m] = acc;
}

__global__ __launch_bounds__(128)
void k_qk3(const float* __restrict__ Wk_lin)
{
    __shared__ float ts[16 * 64];
    int d  = blockIdx.x * 128 + threadIdx.x;
    int m0 = blockIdx.y * 64;
    for (int i = threadIdx.x; i < 16 * 64; i += 128)
        ts[i] = g_t[(i >> 6) * D_ + m0 + (i & 63)];
    __syncthreads();
    float acc[16];
    #pragma unroll
    for (int h = 0; h < 16; h++) acc[h] = 0.f;
    for (int m = 0; m < 64; m++) {
        float w = Wk_lin[(long)(m0 + m) * D_ + d];
        #pragma unroll
        for (int h = 0; h < 16; h++) acc[h] += ts[h*64 + m] * w;
    }
    #pragma unroll
    for (int h = 0; h < 16; h++) atomicAdd(&g_qk[h*D_ + d], acc[h]);
}

__global__ __launch_bounds__(256)
void k_split3(const float* __restrict__ W0, const float* __restrict__ W1,
              const float* __restrict__ W2)
{
    int blk = blockIdx.x;
    int m = blk >> 9;
    int off = (blk & 511) * 1024;
    const float* W = (m == 0) ? W0 : (m == 1) ? W1 : W2;
    bf16* hi = (m == 0) ? g_wo_hi : (m == 1) ? g_wvi_hi : g_wvl_hi;
    bf16* lo = (m == 0) ? g_wo_lo : (m == 1) ? g_wvi_lo : g_wvl_lo;
    #pragma unroll
    for (int i = 0; i < 4; i++) {
        int idx = off + i * 256 + threadIdx.x;
        float2 v = ((const float2*)W)[idx];
        bf16 hx = __float2bfloat16_rn(v.x), hy = __float2bfloat16_rn(v.y);
        bf16 lx = __float2bfloat16_rn(v.x - __bfloat162float(hx));
        bf16 ly = __float2bfloat16_rn(v.y - __bfloat162float(hy));
        ((u32*)hi)[idx] = (u32)__bfloat16_as_ushort(hx) | ((u32)__bfloat16_as_ushort(hy) << 16);
        ((u32*)lo)[idx] = (u32)__bfloat16_as_ushort(lx) | ((u32)__bfloat16_as_ushort(ly) << 16);
    }
}

// ================= GEMM machinery (R8 + NS template) =================
// 64 chunks of K=32. hi phase (c<32): A=Ahi vs Bhi+Blo; lo: A=Alo vs Bhi.
#define LS 40
#define NCHN 64

template<int BN, bool BTRANS>
__device__ __forceinline__
void load_tile(bf16* As, bf16* Bs, int c,
               const bf16* Ahi, const bf16* Alo, int lda, int bm,
               const bf16* Bhi, const bf16* Blo, int ldb, int bn, int t)
{
    const bool hip = c < 32;
    const int kb = (c & 31) * 32;
    const bf16* Ap = hip ? Ahi : Alo;
    {
        int row = t >> 1, ch = (t & 1) * 2;
        const bf16* src = Ap + (long)(bm + row) * lda + kb + ch * 8;
        u32 dst = smem_u32(&As[row*LS + ch*8]);
        CPA(dst, src); CPA(dst + 16, src + 8);
    }
    if (!BTRANS) {
        int row = t >> 2, ch = t & 3;
        const bf16* s0 = Bhi + (long)(bn + row) * ldb + kb + ch * 8;
        CPA(smem_u32(&Bs[row*LS + ch*8]), s0);
        if (hip) {
            const bf16* s1 = Blo + (long)(bn + row) * ldb + kb + ch * 8;
            CPA(smem_u32(&Bs[BN*LS + row*LS + ch*8]), s1);
        }
    } else {
        int mrow = t >> 3, nc0 = (t & 7) * 16;
        {
            const bf16* s0 = Bhi + (long)(kb + mrow) * ldb + bn + nc0;
            bf16 tmp[16];
            *(uint4*)tmp = *(const uint4*)s0;
            *(uint4*)(tmp + 8) = *(const uint4*)(s0 + 8);
            #pragma unroll
            for (int j = 0; j < 16; j++) Bs[(nc0 + j)*LS + mrow] = tmp[j];
        }
        if (hip) {
            const bf16* s1 = Blo + (long)(kb + mrow) * ldb + bn + nc0;
            bf16 tmp[16];
            *(uint4*)tmp = *(const uint4*)s1;
            *(uint4*)(tmp + 8) = *(const uint4*)(s1 + 8);
            #pragma unroll
            for (int j = 0; j < 16; j++) Bs[BN*LS + (nc0 + j)*LS + mrow] = tmp[j];
        }
    }
}

template<int BN>
__device__ __forceinline__
void mma_part(const bf16* Bp, const u32 (&a)[2][4], float (&acc)[2][BN/16][4],
              int kk, int lane, int wn)
{
    constexpr int NTN = BN / 16;
    #pragma unroll
    for (int nt = 0; nt < NTN; nt++) {
        int l = lane & 15;
        u32 bd = smem_u32(&Bp[(wn*(BN/2) + nt*8 + (l & 7))*LS + kk + ((l >> 3) << 3)]);
        u32 b0, b1;
        asm volatile("ldmatrix.sync.aligned.m8n8.x2.shared.b16 {%0,%1}, [%2];"
            : "=r"(b0), "=r"(b1) : "r"(bd));
        #pragma unroll
        for (int mt = 0; mt < 2; mt++) {
            asm volatile(
                "mma.sync.aligned.m16n8k16.row.col.f32.bf16.bf16.f32 "
                "{%0,%1,%2,%3}, {%4,%5,%6,%7}, {%8,%9}, {%0,%1,%2,%3};"
                : "+f"(acc[mt][nt][0]), "+f"(acc[mt][nt][1]),
                  "+f"(acc[mt][nt][2]), "+f"(acc[mt][nt][3])
                : "r"(a[mt][0]), "r"(a[mt][1]), "r"(a[mt][2]), "r"(a[mt][3]),
                  "r"(b0), "r"(b1));
        }
    }
}

template<int BN>
__device__ __forceinline__
void compute_tile(const bf16* As, const bf16* Bs, float (&acc)[2][BN/16][4],
                  int t, bool hip)
{
    int lane = t & 31, wid = t >> 5;
    int wm = wid & 3, wn = wid >> 2;
    #pragma unroll
    for (int kk = 0; kk < 32; kk += 16) {
        u32 a[2][4];
        #pragma unroll
        for (int mt = 0; mt < 2; mt++) {
            u32 ad = smem_u32(&As[(wm*32 + mt*16 + (lane & 15))*LS + kk + ((lane >> 4) << 3)]);
            asm volatile("ldmatrix.sync.aligned.m8n8.x4.shared.b16 {%0,%1,%2,%3}, [%4];"
                : "=r"(a[mt][0]), "=r"(a[mt][1]), "=r"(a[mt][2]), "=r"(a[mt][3]) : "r"(ad));
        }
        mma_part<BN>(Bs, a, acc, kk, lane, wn);
        if (hip) mma_part<BN>(Bs + BN*LS, a, acc, kk, lane, wn);
    }
}

// NS-stage pipeline. NS=2 reproduces R8 exactly; NS=3 runs loads 2 ahead.
template<int BN, bool BTRANS, bool SPLIT, int NS>
__device__ void mma_gemm_body(char* smem,
    const bf16* Ahi, const bf16* Alo, int lda,
    const bf16* Bhi, const bf16* Blo, int ldb,
    float* Cf, bf16* Chi, bf16* Clo, int ldc,
    const float* bias, int bm, int bn)
{
    constexpr int NTN = BN / 16;
    constexpr int ASTG = 128 * LS;
    constexpr int BSTG = 2 * BN * LS;
    bf16* Asg = (bf16*)smem;
    bf16* Bsg = (bf16*)(smem + NS * ASTG * 2);
    const int t = threadIdx.x;
    float acc[2][NTN][4];
    #pragma unroll
    for (int i = 0; i < 2; i++)
        #pragma unroll
        for (int j = 0; j < NTN; j++)
            #pragma unroll
            for (int q = 0; q < 4; q++) acc[i][j][q] = 0.f;

    #pragma unroll
    for (int c = 0; c < NS - 1; c++) {
        load_tile<BN, BTRANS>(Asg + c*ASTG, Bsg + c*BSTG, c,
                              Ahi, Alo, lda, bm, Bhi, Blo, ldb, bn, t);
        CPC();
    }
    for (int c = 0; c < NCHN; c++) {
        int st = c % NS;
        CPW(NS - 2);            // oldest outstanding group (chunk c) complete
        __syncthreads();        // all warps done computing chunk c-1
        int cn = c + NS - 1;
        if (cn < NCHN) {
            load_tile<BN, BTRANS>(Asg + (cn % NS)*ASTG, Bsg + (cn % NS)*BSTG, cn,
                                  Ahi, Alo, lda, bm, Bhi, Blo, ldb, bn, t);
            CPC();
        }
        compute_tile<BN>(Asg + st*ASTG, Bsg + st*BSTG, acc, t, c < 32);
    }

    int lane = t & 31, wid = t >> 5, wm = wid & 3, wn = wid >> 2;
    int gr = lane >> 2, gc = (lane & 3) * 2;
    #pragma unroll
    for (int mt = 0; mt < 2; mt++) {
        #pragma unroll
        for (int nt = 0; nt < NTN; nt++) {
            int col = bn + wn*(BN/2) + nt*8 + gc;
            float b0 = bias ? bias[col]     : 0.f;
            float b1 = bias ? bias[col + 1] : 0.f;
            long r0 = bm + wm*32 + mt*16 + gr;
            long r1 = r0 + 8;
            float v00 = acc[mt][nt][0] + b0, v01 = acc[mt][nt][1] + b1;
            float v10 = acc[mt][nt][2] + b0, v11 = acc[mt][nt][3] + b1;
            if (SPLIT) {
                store_split(Chi, Clo, r0*ldc + col, v00, v01);
                store_split(Chi, Clo, r1*ldc + col, v10, v11);
            } else {
                *(float2*)&Cf[r0*ldc + col] = make_float2(v00, v01);
                *(float2*)&Cf[r1*ldc + col] = make_float2(v10, v11);
            }
        }
    }
}

template<int BN, bool SPLIT>
__global__ __launch_bounds__(256)
void mma_gemm(const bf16* Ahi, const bf16* Alo, int lda, long gsA,
              const bf16* Bhi, const bf16* Blo, long gsB,
              float* Cf, bf16* Chi, bf16* Clo, long gsC,
              const float* bias, long gsBias)
{
    extern __shared__ char smem[];
    long z = blockIdx.z;
    mma_gemm_body<BN, false, SPLIT, 3>(smem,
        Ahi + z*gsA, Alo + z*gsA, lda,
        Bhi + z*gsB, Blo + z*gsB, 1024,
        Cf  ? Cf  + z*gsC : (float*)0,
        Chi ? Chi + z*gsC : (bf16*)0,
        Clo ? Clo + z*gsC : (bf16*)0, 1024,
        bias ? bias + z*gsBias : (const float*)0,
        blockIdx.x * 128, blockIdx.y * BN);
}

// ================= fused scores + softmax + y (R8, unchanged) ============
#define PX 1028
__device__ __forceinline__ void aggr_body(float* sm, const float* __restrict__ x, int sb)
{
    float* xs  = sm;
    float* att = sm + 16 * PX;

    const int t = threadIdx.x;
    const int s = sb >> 5, b = sb & 31;

    #pragma unroll
    for (int i = 0; i < 16; i++) {
        int f4 = i * 256 + t;
        int e = f4 >> 8, d4 = f4 & 255;
        float4 v = ((const float4*)x)[((long)((s*16 + e)*32 + b)) * 256 + d4];
        *(float4*)&xs[e*PX + d4*4] = v;
    }
    __syncthreads();

    {
        const int h = t >> 4, e = t & 15;
        const float4* xr = (const float4*)&xs[e*PX];
        const float4* qr = (const float4*)&g_qk[h*D_];
        float acc = 0.f;
        #pragma unroll 8
        for (int i = 0; i < 256; i++) {
            float4 a = xr[i], q = qr[i];
            acc += a.x*q.x + a.y*q.y + a.z*q.z + a.w*q.w;
        }
        float mx = acc;
        #pragma unroll
        for (int o = 8; o; o >>= 1) mx = fmaxf(mx, __shfl_xor_sync(0xffffffffu, mx, o, 16));
        float p = __expf(acc - mx);
        float sum = p;
        #pragma unroll
        for (int o = 8; o; o >>= 1) sum += __shfl_xor_sync(0xffffffffu, sum, o, 16);
        att[t] = p / sum;
    }
    __syncthreads();

    float4 acch[16];
    #pragma unroll
    for (int h = 0; h < 16; h++) acch[h] = make_float4(0.f, 0.f, 0.f, 0.f);
    #pragma unroll
    for (int et = 0; et < 4; et++) {
        float4 xv[4];
        #pragma unroll
        for (int e2 = 0; e2 < 4; e2++)
            xv[e2] = *(const float4*)&xs[(et*4 + e2)*PX + t*4];
        #pragma unroll
        for (int h = 0; h < 16; h++) {
            #pragma unroll
            for (int e2 = 0; e2 < 4; e2++) {
                float a = att[h*16 + et*4 + e2];
                acch[h].x = fmaf(a, xv[e2].x, acch[h].x);
                acch[h].y = fmaf(a, xv[e2].y, acch[h].y);
                acch[h].z = fmaf(a, xv[e2].z, acch[h].z);
                acch[h].w = fmaf(a, xv[e2].w, acch[h].w);
            }
        }
    }
    #pragma unroll
    for (int h = 0; h < 16; h++) {
        float4 v = acch[h];
        long base = ((long)sb*16 + h)*1024 + t*4;
        store_split(g_yhi, g_ylo, base,     v.x, v.y);
        store_split(g_yhi, g_ylo, base + 2, v.z, v.w);
    }
}

// fat: blocks [0,64) Wcv = Wv_in @ Wv_lin (mma, BTRANS, NS=2 = R8); rest aggr
#define WCV_BLOCKS 64
__global__ __launch_bounds__(256)
void k_fat(const float* __restrict__ x)
{
    extern __shared__ char sm[];
    if (blockIdx.x < WCV_BLOCKS) {
        int wb = blockIdx.x;
        mma_gemm_body<128, true, true, 2>(sm,
            g_wvi_hi, g_wvi_lo, 1024,
            g_wvl_hi, g_wvl_lo, 1024,
            (float*)0, g_wcv_hi, g_wcv_lo, 1024,
            (const float*)0,
            (wb >> 3) * 128, (wb & 7) * 128);
    } else {
        aggr_body((float*)sm, x, blockIdx.x - WCV_BLOCKS);
    }
}

// ================= launch (R8 schedule) =================
extern "C" void kernel_launch(void* const* d_in, const int* in_sizes, int n_in,
                              void* d_out, int out_size)
{
    const float* x = (const float*)d_in[0];
    int qi = n_in - 13;
    const float* query  = (const float*)d_in[qi + 0];
    const float* Wk_lin = (const float*)d_in[qi + 1];
    const float* Wv_lin = (const float*)d_in[qi + 3];
    const float* bv_lin = (const float*)d_in[qi + 4];
    const float* Wq_in  = (const float*)d_in[qi + 5];
    const float* bq_in  = (const float*)d_in[qi + 6];
    const float* Wk_in  = (const float*)d_in[qi + 7];
    const float* Wv_in  = (const float*)d_in[qi + 9];
    const float* bv_in  = (const float*)d_in[qi + 10];
    const float* Wo     = (const float*)d_in[qi + 11];
    const float* bo     = (const float*)d_in[qi + 12];
    float* out = (float*)d_out;

    float *p_qp, *p_bcv, *p_qk;
    bf16 *p_yhi, *p_ylo, *p_wcvh, *p_wcvl, *p_woh, *p_wol, *p_cth, *p_ctl;
    cudaGetSymbolAddress((void**)&p_qp,   g_qp);
    cudaGetSymbolAddress((void**)&p_bcv,  g_bcv);
    cudaGetSymbolAddress((void**)&p_qk,   g_qk);
    cudaGetSymbolAddress((void**)&p_yhi,  g_yhi);
    cudaGetSymbolAddress((void**)&p_ylo,  g_ylo);
    cudaGetSymbolAddress((void**)&p_wcvh, g_wcv_hi);
    cudaGetSymbolAddress((void**)&p_wcvl, g_wcv_lo);
    cudaGetSymbolAddress((void**)&p_woh,  g_wo_hi);
    cudaGetSymbolAddress((void**)&p_wol,  g_wo_lo);
    cudaGetSymbolAddress((void**)&p_cth,  g_ctx_hi);
    cudaGetSymbolAddress((void**)&p_ctl,  g_ctx_lo);

    const int FAT_SMEM = (16*PX + 256) * 4;              // 66816 >= Wcv NS=2 61440
    const int CTX_SMEM = 3*128*LS*2 + 3*2*64*LS*2;       // 61440 (NS=3)
    const int OUT_SMEM = CTX_SMEM;
    static int attr_set = 0;
    if (!attr_set) {
        cudaFuncSetAttribute(k_fat, cudaFuncAttributeMaxDynamicSharedMemorySize, FAT_SMEM);
        cudaFuncSetAttribute(mma_gemm<64, true>,
                             cudaFuncAttributeMaxDynamicSharedMemorySize, CTX_SMEM);
        cudaFuncSetAttribute(mma_gemm<64, false>,
                             cudaFuncAttributeMaxDynamicSharedMemorySize, OUT_SMEM);
        attr_set = 1;
    }

    // 0. zero qk accumulator
    cudaMemsetAsync(p_qk, 0, H_*D_*sizeof(float), 0);
    // 1. weight splits (single uniform launch)
    k_split3<<<1536, 256>>>(Wo, Wv_in, Wv_lin);
    // 2. qp = (Wq_in @ query + bq_in) / 8
    k_rowdot<<<128, 256>>>(Wq_in, query, bq_in, p_qp, D_, D_, 0.125f);
    // 3. bcv = Wv_in @ bv_lin + bv_in
    k_rowdot<<<128, 256>>>(Wv_in, bv_lin, bv_in, p_bcv, D_, D_, 1.0f);
    // 4. t = fold(qp, Wk_in)
    k_t<<<dim3(4, 16), 256>>>(Wk_in);
    // 5. qk = t @ Wk_lin
    k_qk3<<<dim3(8, 16), 128>>>(Wk_lin);
    // 6. fat: Wcv mma (64 blocks) || scores+softmax+y (2048 blocks)
    k_fat<<<WCV_BLOCKS + SB_, 256, FAT_SMEM>>>(x);
    // 7. ctx_h = y_h @ Wcv_h^T + bcv_h   (NS=3 pipeline)
    mma_gemm<64, true><<<dim3(16, 1, 16), 256, CTX_SMEM>>>(
        p_yhi, p_ylo, H_*D_, (long)D_,
        p_wcvh, p_wcvl, (long)64*D_,
        (float*)0, p_cth, p_ctl, (long)64,
        p_bcv, (long)64);
    // 8. out = ctx @ Wo^T + bo   (NS=3 pipeline)
    mma_gemm<64, false><<<dim3(16, 16, 1), 256, OUT_SMEM>>>(
        p_cth, p_ctl, D_, 0,
        p_woh, p_wol, 0,
        out, (bf16*)0, (bf16*)0, 0,
        bo, 0);
}

// round 15
// speedup vs baseline: 1.6365x; 1.0101x over previous
#include <cuda_runtime.h>
#include <cuda_bf16.h>
#include <math.h>

#define S_  64
#define E_  16
#define B_  32
#define D_  1024
#define H_  16
#define SB_ (S_*B_)

typedef unsigned long long u64;
typedef unsigned int u32;
typedef __nv_bfloat16 bf16;

// ---------------- device scratch (R8 layout) ----------------
__device__ float g_qp [D_];
__device__ float g_t  [H_*D_];
__device__ float g_qk [H_*D_];
__device__ float g_bcv[D_];
__device__ bf16 g_yhi[SB_*H_*D_];
__device__ bf16 g_ylo[SB_*H_*D_];
__device__ bf16 g_wvi_hi[D_*D_], g_wvi_lo[D_*D_];
__device__ bf16 g_wvl_hi[D_*D_], g_wvl_lo[D_*D_];
__device__ bf16 g_wcv_hi[D_*D_], g_wcv_lo[D_*D_];
__device__ bf16 g_wo_hi [D_*D_], g_wo_lo [D_*D_];
__device__ bf16 g_ctx_hi[SB_*D_], g_ctx_lo[SB_*D_];

// ---------------- helpers ----------------
__device__ __forceinline__ u32 smem_u32(const void* p) {
    u32 a; asm("{ .reg .u64 t; cvta.to.shared.u64 t, %1; cvt.u32.u64 %0, t; }"
               : "=r"(a) : "l"(p)); return a;
}
#define CPA(dst, src) \
    asm volatile("cp.async.cg.shared.global [%0], [%1], 16;" :: "r"(dst), "l"(src))
#define CPC() asm volatile("cp.async.commit_group;" ::: "memory")
#define CPW(n) asm volatile("cp.async.wait_group %0;" :: "n"(n) : "memory")

__device__ __forceinline__ void store_split(bf16* hi, bf16* lo, long idx,
                                            float v0, float v1) {
    bf16 h0 = __float2bfloat16_rn(v0), h1 = __float2bfloat16_rn(v1);
    bf16 l0 = __float2bfloat16_rn(v0 - __bfloat162float(h0));
    bf16 l1 = __float2bfloat16_rn(v1 - __bfloat162float(h1));
    *(u32*)&hi[idx] = (u32)__bfloat16_as_ushort(h0) | ((u32)__bfloat16_as_ushort(h1) << 16);
    *(u32*)&lo[idx] = (u32)__bfloat16_as_ushort(l0) | ((u32)__bfloat16_as_ushort(l1) << 16);
}

// ================= front-end =================
__device__ __forceinline__
void rowdot_warp(const float* __restrict__ W, const float* __restrict__ v,
                 const float* __restrict__ bias, float* __restrict__ out,
                 int w, int lane, float scale)
{
    const float4* row4 = (const float4*)(W + (long)w * D_);
    const float4* v4   = (const float4*)v;
    float acc = 0.f;
    #pragma unroll 8
    for (int c = lane; c < D_/4; c += 32) {
        float4 a = row4[c], b = v4[c];
        acc += a.x*b.x + a.y*b.y + a.z*b.z + a.w*b.w;
    }
    #pragma unroll
    for (int o = 16; o; o >>= 1) acc += __shfl_xor_sync(0xffffffffu, acc, o);
    if (!lane) out[w] = (acc + bias[w]) * scale;
}

// both 1024-row rowdots in one uniform launch: blk<128 -> qp, else -> bcv
__global__ void k_row2(const float* __restrict__ Wq_in, const float* __restrict__ query,
                       const float* __restrict__ bq_in,
                       const float* __restrict__ Wv_in, const float* __restrict__ bv_lin,
                       const float* __restrict__ bv_in)
{
    int t = threadIdx.x;
    if (blockIdx.x < 128) {
        rowdot_warp(Wq_in, query, bq_in, g_qp,
                    blockIdx.x * 8 + (t >> 5), t & 31, 0.125f);
    } else {
        rowdot_warp(Wv_in, bv_lin, bv_in, g_bcv,
                    (blockIdx.x - 128) * 8 + (t >> 5), t & 31, 1.0f);
    }
}

// wider grid: 128 blocks x 128 threads (m-chunks of 128)
__global__ __launch_bounds__(128)
void k_t(const float* __restrict__ Wk_in)
{
    int h = blockIdx.y;
    int m = blockIdx.x * 128 + threadIdx.x;
    float acc = 0.f;
    #pragma unroll 8
    for (int j = 0; j < 64; j++)
        acc += g_qp[h*64 + j] * Wk_in[(long)(h*64 + j) * D_ + m];
    g_t[h*D_ + m] = acc;
}

__global__ __launch_bounds__(128)
void k_qk3(const float* __restrict__ Wk_lin)
{
    __shared__ float ts[16 * 64];
    int d  = blockIdx.x * 128 + threadIdx.x;
    int m0 = blockIdx.y * 64;
    for (int i = threadIdx.x; i < 16 * 64; i += 128)
        ts[i] = g_t[(i >> 6) * D_ + m0 + (i & 63)];
    __syncthreads();
    float acc[16];
    #pragma unroll
    for (int h = 0; h < 16; h++) acc[h] = 0.f;
    for (int m = 0; m < 64; m++) {
        float w = Wk_lin[(long)(m0 + m) * D_ + d];
        #pragma unroll
        for (int h = 0; h < 16; h++) acc[h] += ts[h*64 + m] * w;
    }
    #pragma unroll
    for (int h = 0; h < 16; h++) atomicAdd(&g_qk[h*D_ + d], acc[h]);
}

__global__ __launch_bounds__(256)
void k_split3(const float* __restrict__ W0, const float* __restrict__ W1,
              const float* __restrict__ W2)
{
    int blk = blockIdx.x;
    int m = blk >> 9;
    int off = (blk & 511) * 1024;
    const float* W = (m == 0) ? W0 : (m == 1) ? W1 : W2;
    bf16* hi = (m == 0) ? g_wo_hi : (m == 1) ? g_wvi_hi : g_wvl_hi;
    bf16* lo = (m == 0) ? g_wo_lo : (m == 1) ? g_wvi_lo : g_wvl_lo;
    #pragma unroll
    for (int i = 0; i < 4; i++) {
        int idx = off + i * 256 + threadIdx.x;
        float2 v = ((const float2*)W)[idx];
        bf16 hx = __float2bfloat16_rn(v.x), hy = __float2bfloat16_rn(v.y);
        bf16 lx = __float2bfloat16_rn(v.x - __bfloat162float(hx));
        bf16 ly = __float2bfloat16_rn(v.y - __bfloat162float(hy));
        ((u32*)hi)[idx] = (u32)__bfloat16_as_ushort(hx) | ((u32)__bfloat16_as_ushort(hy) << 16);
        ((u32*)lo)[idx] = (u32)__bfloat16_as_ushort(lx) | ((u32)__bfloat16_as_ushort(ly) << 16);
    }
}

// ================= GEMM machinery =================
#define LS 40
#define NCHN 64

template<int BN, bool BTRANS>
__device__ __forceinline__
void load_tile(bf16* As, bf16* Bs, int c,
               const bf16* Ahi, const bf16* Alo, int lda, int bm,
               const bf16* Bhi, const bf16* Blo, int ldb, int bn, int t)
{
    const bool hip = c < 32;
    const int kb = (c & 31) * 32;
    const bf16* Ap = hip ? Ahi : Alo;
    {
        int row = t >> 1, ch = (t & 1) * 2;
        const bf16* src = Ap + (long)(bm + row) * lda + kb + ch * 8;
        u32 dst = smem_u32(&As[row*LS + ch*8]);
        CPA(dst, src); CPA(dst + 16, src + 8);
    }
    if (!BTRANS) {
        int row = t >> 2, ch = t & 3;
        const bf16* s0 = Bhi + (long)(bn + row) * ldb + kb + ch * 8;
        CPA(smem_u32(&Bs[row*LS + ch*8]), s0);
        if (hip) {
            const bf16* s1 = Blo + (long)(bn + row) * ldb + kb + ch * 8;
            CPA(smem_u32(&Bs[BN*LS + row*LS + ch*8]), s1);
        }
    } else {
        int mrow = t >> 3, nc0 = (t & 7) * 16;
        {
            const bf16* s0 = Bhi + (long)(kb + mrow) * ldb + bn + nc0;
            bf16 tmp[16];
            *(uint4*)tmp = *(const uint4*)s0;
            *(uint4*)(tmp + 8) = *(const uint4*)(s0 + 8);
            #pragma unroll
            for (int j = 0; j < 16; j++) Bs[(nc0 + j)*LS + mrow] = tmp[j];
        }
        if (hip) {
            const bf16* s1 = Blo + (long)(kb + mrow) * ldb + bn + nc0;
            bf16 tmp[16];
            *(uint4*)tmp = *(const uint4*)s1;
            *(uint4*)(tmp + 8) = *(const uint4*)(s1 + 8);
            #pragma unroll
            for (int j = 0; j < 16; j++) Bs[BN*LS + (nc0 + j)*LS + mrow] = tmp[j];
        }
    }
}

// B via ldmatrix.x4: two n-tiles per LDSM.
// lane group g=l>>3: row = base + ntp*16 + (g&1)*8 + (l&7), col = kk + (g>>1)*8
// frag nt=2*ntp -> {r0, r2}; nt=2*ntp+1 -> {r1, r3}
template<int BN>
__device__ __forceinline__
void mma_part(const bf16* Bp, const u32 (&a)[2][4], float (&acc)[2][BN/16][4],
              int kk, int lane, int wn)
{
    constexpr int NTN = BN / 16;
    int g = lane >> 3;
    #pragma unroll
    for (int ntp = 0; ntp < NTN/2; ntp++) {
        u32 bd = smem_u32(&Bp[(wn*(BN/2) + ntp*16 + ((g & 1) << 3) + (lane & 7))*LS
                              + kk + ((g >> 1) << 3)]);
        u32 r0, r1, r2, r3;
        asm volatile("ldmatrix.sync.aligned.m8n8.x4.shared.b16 {%0,%1,%2,%3}, [%4];"
            : "=r"(r0), "=r"(r1), "=r"(r2), "=r"(r3) : "r"(bd));
        #pragma unroll
        for (int mt = 0; mt < 2; mt++) {
            asm volatile(
                "mma.sync.aligned.m16n8k16.row.col.f32.bf16.bf16.f32 "
                "{%0,%1,%2,%3}, {%4,%5,%6,%7}, {%8,%9}, {%0,%1,%2,%3};"
                : "+f"(acc[mt][2*ntp][0]), "+f"(acc[mt][2*ntp][1]),
                  "+f"(acc[mt][2*ntp][2]), "+f"(acc[mt][2*ntp][3])
                : "r"(a[mt][0]), "r"(a[mt][1]), "r"(a[mt][2]), "r"(a[mt][3]),
                  "r"(r0), "r"(r2));
            asm volatile(
                "mma.sync.aligned.m16n8k16.row.col.f32.bf16.bf16.f32 "
                "{%0,%1,%2,%3}, {%4,%5,%6,%7}, {%8,%9}, {%0,%1,%2,%3};"
                : "+f"(acc[mt][2*ntp+1][0]), "+f"(acc[mt][2*ntp+1][1]),
                  "+f"(acc[mt][2*ntp+1][2]), "+f"(acc[mt][2*ntp+1][3])
                : "r"(a[mt][0]), "r"(a[mt][1]), "r"(a[mt][2]), "r"(a[mt][3]),
                  "r"(r1), "r"(r3));
        }
    }
}

template<int BN>
__device__ __forceinline__
void compute_tile(const bf16* As, const bf16* Bs, float (&acc)[2][BN/16][4],
                  int t, bool hip)
{
    int lane = t & 31, wid = t >> 5;
    int wm = wid & 3, wn = wid >> 2;
    #pragma unroll
    for (int kk = 0; kk < 32; kk += 16) {
        u32 a[2][4];
        #pragma unroll
        for (int mt = 0; mt < 2; mt++) {
            u32 ad = smem_u32(&As[(wm*32 + mt*16 + (lane & 15))*LS + kk + ((lane >> 4) << 3)]);
            asm volatile("ldmatrix.sync.aligned.m8n8.x4.shared.b16 {%0,%1,%2,%3}, [%4];"
                : "=r"(a[mt][0]), "=r"(a[mt][1]), "=r"(a[mt][2]), "=r"(a[mt][3]) : "r"(ad));
        }
        mma_part<BN>(Bs, a, acc, kk, lane, wn);
        if (hip) mma_part<BN>(Bs + BN*LS, a, acc, kk, lane, wn);
    }
}

// NS-stage pipeline (NS=2 = proven R8 schedule; NS=3 loads 2 chunks ahead)
template<int BN, bool BTRANS, bool SPLIT, int NS>
__device__ void mma_gemm_body(char* smem,
    const bf16* Ahi, const bf16* Alo, int lda,
    const bf16* Bhi, const bf16* Blo, int ldb,
    float* Cf, bf16* Chi, bf16* Clo, int ldc,
    const float* bias, int bm, int bn)
{
    constexpr int NTN = BN / 16;
    constexpr int ASTG = 128 * LS;
    constexpr int BSTG = 2 * BN * LS;
    bf16* Asg = (bf16*)smem;
    bf16* Bsg = (bf16*)(smem + NS * ASTG * 2);
    const int t = threadIdx.x;
    float acc[2][NTN][4];
    #pragma unroll
    for (int i = 0; i < 2; i++)
        #pragma unroll
        for (int j = 0; j < NTN; j++)
            #pragma unroll
            for (int q = 0; q < 4; q++) acc[i][j][q] = 0.f;

    #pragma unroll
    for (int c = 0; c < NS - 1; c++) {
        load_tile<BN, BTRANS>(Asg + c*ASTG, Bsg + c*BSTG, c,
                              Ahi, Alo, lda, bm, Bhi, Blo, ldb, bn, t);
        CPC();
    }
    for (int c = 0; c < NCHN; c++) {
        int st = c % NS;
        CPW(NS - 2);
        __syncthreads();
        int cn = c + NS - 1;
        if (cn < NCHN) {
            load_tile<BN, BTRANS>(Asg + (cn % NS)*ASTG, Bsg + (cn % NS)*BSTG, cn,
                                  Ahi, Alo, lda, bm, Bhi, Blo, ldb, bn, t);
            CPC();
        }
        compute_tile<BN>(Asg + st*ASTG, Bsg + st*BSTG, acc, t, c < 32);
    }

    int lane = t & 31, wid = t >> 5, wm = wid & 3, wn = wid >> 2;
    int gr = lane >> 2, gc = (lane & 3) * 2;
    #pragma unroll
    for (int mt = 0; mt < 2; mt++) {
        #pragma unroll
        for (int nt = 0; nt < NTN; nt++) {
            int col = bn + wn*(BN/2) + nt*8 + gc;
            float b0 = bias ? bias[col]     : 0.f;
            float b1 = bias ? bias[col + 1] : 0.f;
            long r0 = bm + wm*32 + mt*16 + gr;
            long r1 = r0 + 8;
            float v00 = acc[mt][nt][0] + b0, v01 = acc[mt][nt][1] + b1;
            float v10 = acc[mt][nt][2] + b0, v11 = acc[mt][nt][3] + b1;
            if (SPLIT) {
                store_split(Chi, Clo, r0*ldc + col, v00, v01);
                store_split(Chi, Clo, r1*ldc + col, v10, v11);
            } else {
                *(float2*)&Cf[r0*ldc + col] = make_float2(v00, v01);
                *(float2*)&Cf[r1*ldc + col] = make_float2(v10, v11);
            }
        }
    }
}

template<int BN, bool SPLIT>
__global__ __launch_bounds__(256)
void mma_gemm(const bf16* Ahi, const bf16* Alo, int lda, long gsA,
              const bf16* Bhi, const bf16* Blo, long gsB,
              float* Cf, bf16* Chi, bf16* Clo, long gsC,
              const float* bias, long gsBias)
{
    extern __shared__ char smem[];
    long z = blockIdx.z;
    mma_gemm_body<BN, false, SPLIT, 3>(smem,
        Ahi + z*gsA, Alo + z*gsA, lda,
        Bhi + z*gsB, Blo + z*gsB, 1024,
        Cf  ? Cf  + z*gsC : (float*)0,
        Chi ? Chi + z*gsC : (bf16*)0,
        Clo ? Clo + z*gsC : (bf16*)0, 1024,
        bias ? bias + z*gsBias : (const float*)0,
        blockIdx.x * 128, blockIdx.y * BN);
}

// ================= fused scores + softmax + y (unchanged) ============
#define PX 1028
__device__ __forceinline__ void aggr_body(float* sm, const float* __restrict__ x, int sb)
{
    float* xs  = sm;
    float* att = sm + 16 * PX;

    const int t = threadIdx.x;
    const int s = sb >> 5, b = sb & 31;

    #pragma unroll
    for (int i = 0; i < 16; i++) {
        int f4 = i * 256 + t;
        int e = f4 >> 8, d4 = f4 & 255;
        float4 v = ((const float4*)x)[((long)((s*16 + e)*32 + b)) * 256 + d4];
        *(float4*)&xs[e*PX + d4*4] = v;
    }
    __syncthreads();

    {
        const int h = t >> 4, e = t & 15;
        const float4* xr = (const float4*)&xs[e*PX];
        const float4* qr = (const float4*)&g_qk[h*D_];
        float acc = 0.f;
        #pragma unroll 8
        for (int i = 0; i < 256; i++) {
            float4 a = xr[i], q = qr[i];
            acc += a.x*q.x + a.y*q.y + a.z*q.z + a.w*q.w;
        }
        float mx = acc;
        #pragma unroll
        for (int o = 8; o; o >>= 1) mx = fmaxf(mx, __shfl_xor_sync(0xffffffffu, mx, o, 16));
        float p = __expf(acc - mx);
        float sum = p;
        #pragma unroll
        for (int o = 8; o; o >>= 1) sum += __shfl_xor_sync(0xffffffffu, sum, o, 16);
        att[t] = p / sum;
    }
    __syncthreads();

    float4 acch[16];
    #pragma unroll
    for (int h = 0; h < 16; h++) acch[h] = make_float4(0.f, 0.f, 0.f, 0.f);
    #pragma unroll
    for (int et = 0; et < 4; et++) {
        float4 xv[4];
        #pragma unroll
        for (int e2 = 0; e2 < 4; e2++)
            xv[e2] = *(const float4*)&xs[(et*4 + e2)*PX + t*4];
        #pragma unroll
        for (int h = 0; h < 16; h++) {
            #pragma unroll
            for (int e2 = 0; e2 < 4; e2++) {
                float a = att[h*16 + et*4 + e2];
                acch[h].x = fmaf(a, xv[e2].x, acch[h].x);
                acch[h].y = fmaf(a, xv[e2].y, acch[h].y);
                acch[h].z = fmaf(a, xv[e2].z, acch[h].z);
                acch[h].w = fmaf(a, xv[e2].w, acch[h].w);
            }
        }
    }
    #pragma unroll
    for (int h = 0; h < 16; h++) {
        float4 v = acch[h];
        long base = ((long)sb*16 + h)*1024 + t*4;
        store_split(g_yhi, g_ylo, base,     v.x, v.y);
        store_split(g_yhi, g_ylo, base + 2, v.z, v.w);
    }
}

// fat: blocks [0,64) Wcv (mma, BTRANS, NS=2); rest aggr
#define WCV_BLOCKS 64
__global__ __launch_bounds__(256)
void k_fat(const float* __restrict__ x)
{
    extern __shared__ char sm[];
    if (blockIdx.x < WCV_BLOCKS) {
        int wb = blockIdx.x;
        mma_gemm_body<128, true, true, 2>(sm,
            g_wvi_hi, g_wvi_lo, 1024,
            g_wvl_hi, g_wvl_lo, 1024,
            (float*)0, g_wcv_hi, g_wcv_lo, 1024,
            (const float*)0,
            (wb >> 3) * 128, (wb & 7) * 128);
    } else {
        aggr_body((float*)sm, x, blockIdx.x - WCV_BLOCKS);
    }
}

// ================= launch =================
extern "C" void kernel_launch(void* const* d_in, const int* in_sizes, int n_in,
                              void* d_out, int out_size)
{
    const float* x = (const float*)d_in[0];
    int qi = n_in - 13;
    const float* query  = (const float*)d_in[qi + 0];
    const float* Wk_lin = (const float*)d_in[qi + 1];
    const float* Wv_lin = (const float*)d_in[qi + 3];
    const float* bv_lin = (const float*)d_in[qi + 4];
    const float* Wq_in  = (const float*)d_in[qi + 5];
    const float* bq_in  = (const float*)d_in[qi + 6];
    const float* Wk_in  = (const float*)d_in[qi + 7];
    const float* Wv_in  = (const float*)d_in[qi + 9];
    const float* bv_in  = (const float*)d_in[qi + 10];
    const float* Wo     = (const float*)d_in[qi + 11];
    const float* bo     = (const float*)d_in[qi + 12];
    float* out = (float*)d_out;

    float *p_bcv, *p_qk;
    bf16 *p_yhi, *p_ylo, *p_wcvh, *p_wcvl, *p_woh, *p_wol, *p_cth, *p_ctl;
    cudaGetSymbolAddress((void**)&p_bcv,  g_bcv);
    cudaGetSymbolAddress((void**)&p_qk,   g_qk);
    cudaGetSymbolAddress((void**)&p_yhi,  g_yhi);
    cudaGetSymbolAddress((void**)&p_ylo,  g_ylo);
    cudaGetSymbolAddress((void**)&p_wcvh, g_wcv_hi);
    cudaGetSymbolAddress((void**)&p_wcvl, g_wcv_lo);
    cudaGetSymbolAddress((void**)&p_woh,  g_wo_hi);
    cudaGetSymbolAddress((void**)&p_wol,  g_wo_lo);
    cudaGetSymbolAddress((void**)&p_cth,  g_ctx_hi);
    cudaGetSymbolAddress((void**)&p_ctl,  g_ctx_lo);

    const int FAT_SMEM = (16*PX + 256) * 4;
    const int CTX_SMEM = 3*128*LS*2 + 3*2*64*LS*2;   // 61440
    const int OUT_SMEM = CTX_SMEM;
    static int attr_set = 0;
    if (!attr_set) {
        cudaFuncSetAttribute(k_fat, cudaFuncAttributeMaxDynamicSharedMemorySize, FAT_SMEM);
        cudaFuncSetAttribute(mma_gemm<64, true>,
                             cudaFuncAttributeMaxDynamicSharedMemorySize, CTX_SMEM);
        cudaFuncSetAttribute(mma_gemm<64, false>,
                             cudaFuncAttributeMaxDynamicSharedMemorySize, OUT_SMEM);
        attr_set = 1;
    }

    // 0. zero qk accumulator
    cudaMemsetAsync(p_qk, 0, H_*D_*sizeof(float), 0);
    // 1. weight splits
    k_split3<<<1536, 256>>>(Wo, Wv_in, Wv_lin);
    // 2. qp + bcv in one uniform launch
    k_row2<<<256, 256>>>(Wq_in, query, bq_in, Wv_in, bv_lin, bv_in);
    // 3. t = fold(qp, Wk_in)  (wider grid)
    k_t<<<dim3(8, 16), 128>>>(Wk_in);
    // 4. qk = t @ Wk_lin
    k_qk3<<<dim3(8, 16), 128>>>(Wk_lin);
    // 5. fat: Wcv mma (64 blocks) || scores+softmax+y (2048 blocks)
    k_fat<<<WCV_BLOCKS + SB_, 256, FAT_SMEM>>>(x);
    // 6. ctx_h = y_h @ Wcv_h^T + bcv_h   (NS=3)
    mma_gemm<64, true><<<dim3(16, 1, 16), 256, CTX_SMEM>>>(
        p_yhi, p_ylo, H_*D_, (long)D_,
        p_wcvh, p_wcvl, (long)64*D_,
        (float*)0, p_cth, p_ctl, (long)64,
        p_bcv, (long)64);
    // 7. out = ctx @ Wo^T + bo   (NS=3)
    mma_gemm<64, false><<<dim3(16, 16, 1), 256, OUT_SMEM>>>(
        p_cth, p_ctl, D_, 0,
        p_woh, p_wol, 0,
        out, (bf16*)0, (bf16*)0, 0,
        bo, 0);
}

// round 16
// speedup vs baseline: 1.6988x; 1.0381x over previous
#include <cuda_runtime.h>
#include <cuda_bf16.h>
#include <math.h>

#define S_  64
#define E_  16
#define B_  32
#define D_  1024
#define H_  16
#define SB_ (S_*B_)

typedef unsigned long long u64;
typedef unsigned int u32;
typedef __nv_bfloat16 bf16;

// ---------------- device scratch ----------------
__device__ float g_qp [D_];
__device__ float g_t  [H_*D_];
__device__ float g_qk [H_*D_];
__device__ float g_bcv[D_];
__device__ bf16 g_yhi[SB_*H_*D_];
__device__ bf16 g_ylo[SB_*H_*D_];
__device__ bf16 g_wvi_hi[D_*D_], g_wvi_lo[D_*D_];
__device__ bf16 g_wvl_hi[D_*D_], g_wvl_lo[D_*D_];
__device__ bf16 g_wcv_hi[D_*D_], g_wcv_lo[D_*D_];
__device__ bf16 g_wo_hi [D_*D_], g_wo_lo [D_*D_];
__device__ bf16 g_ctx_hi[SB_*D_], g_ctx_lo[SB_*D_];

// ---------------- helpers ----------------
__device__ __forceinline__ u32 smem_u32(const void* p) {
    u32 a; asm("{ .reg .u64 t; cvta.to.shared.u64 t, %1; cvt.u32.u64 %0, t; }"
               : "=r"(a) : "l"(p)); return a;
}
#define CPA(dst, src) \
    asm volatile("cp.async.cg.shared.global [%0], [%1], 16;" :: "r"(dst), "l"(src))
#define CPC() asm volatile("cp.async.commit_group;" ::: "memory")
#define CPW(n) asm volatile("cp.async.wait_group %0;" :: "n"(n) : "memory")

__device__ __forceinline__ void store_split(bf16* hi, bf16* lo, long idx,
                                            float v0, float v1) {
    bf16 h0 = __float2bfloat16_rn(v0), h1 = __float2bfloat16_rn(v1);
    bf16 l0 = __float2bfloat16_rn(v0 - __bfloat162float(h0));
    bf16 l1 = __float2bfloat16_rn(v1 - __bfloat162float(h1));
    *(u32*)&hi[idx] = (u32)__bfloat16_as_ushort(h0) | ((u32)__bfloat16_as_ushort(h1) << 16);
    *(u32*)&lo[idx] = (u32)__bfloat16_as_ushort(l0) | ((u32)__bfloat16_as_ushort(l1) << 16);
}

// ================= front-end =================
__device__ __forceinline__
void rowdot_warp(const float* __restrict__ W, const float* __restrict__ v,
                 const float* __restrict__ bias, float* __restrict__ out,
                 int w, int lane, float scale)
{
    const float4* row4 = (const float4*)(W + (long)w * D_);
    const float4* v4   = (const float4*)v;
    float acc = 0.f;
    #pragma unroll 8
    for (int c = lane; c < D_/4; c += 32) {
        float4 a = row4[c], b = v4[c];
        acc += a.x*b.x + a.y*b.y + a.z*b.z + a.w*b.w;
    }
    #pragma unroll
    for (int o = 16; o; o >>= 1) acc += __shfl_xor_sync(0xffffffffu, acc, o);
    if (!lane) out[w] = (acc + bias[w]) * scale;
}

__global__ void k_row2(const float* __restrict__ Wq_in, const float* __restrict__ query,
                       const float* __restrict__ bq_in,
                       const float* __restrict__ Wv_in, const float* __restrict__ bv_lin,
                       const float* __restrict__ bv_in)
{
    int t = threadIdx.x;
    if (blockIdx.x < 128) {
        rowdot_warp(Wq_in, query, bq_in, g_qp,
                    blockIdx.x * 8 + (t >> 5), t & 31, 0.125f);
    } else {
        rowdot_warp(Wv_in, bv_lin, bv_in, g_bcv,
                    (blockIdx.x - 128) * 8 + (t >> 5), t & 31, 1.0f);
    }
}

__global__ __launch_bounds__(128)
void k_t(const float* __restrict__ Wk_in)
{
    int h = blockIdx.y;
    int m = blockIdx.x * 128 + threadIdx.x;
    float acc = 0.f;
    #pragma unroll 8
    for (int j = 0; j < 64; j++)
        acc += g_qp[h*64 + j] * Wk_in[(long)(h*64 + j) * D_ + m];
    g_t[h*D_ + m] = acc;
}

// split-K qk: m-chunks of 32, batched Wk_lin loads (MLP=8)
__global__ __launch_bounds__(128)
void k_qk3(const float* __restrict__ Wk_lin)
{
    __shared__ float ts[16 * 32];
    int d  = blockIdx.x * 128 + threadIdx.x;
    int m0 = blockIdx.y * 32;
    for (int i = threadIdx.x; i < 16 * 32; i += 128)
        ts[i] = g_t[(i >> 5) * D_ + m0 + (i & 31)];
    __syncthreads();
    float acc[16];
    #pragma unroll
    for (int h = 0; h < 16; h++) acc[h] = 0.f;
    #pragma unroll
    for (int mb = 0; mb < 32; mb += 8) {
        float w[8];
        #pragma unroll
        for (int u = 0; u < 8; u++)
            w[u] = Wk_lin[(long)(m0 + mb + u) * D_ + d];
        #pragma unroll
        for (int u = 0; u < 8; u++)
            #pragma unroll
            for (int h = 0; h < 16; h++)
                acc[h] += ts[h*32 + mb + u] * w[u];
    }
    #pragma unroll
    for (int h = 0; h < 16; h++) atomicAdd(&g_qk[h*D_ + d], acc[h]);
}

__global__ __launch_bounds__(256)
void k_split3(const float* __restrict__ W0, const float* __restrict__ W1,
              const float* __restrict__ W2)
{
    int blk = blockIdx.x;
    int m = blk >> 9;
    int off = (blk & 511) * 1024;
    const float* W = (m == 0) ? W0 : (m == 1) ? W1 : W2;
    bf16* hi = (m == 0) ? g_wo_hi : (m == 1) ? g_wvi_hi : g_wvl_hi;
    bf16* lo = (m == 0) ? g_wo_lo : (m == 1) ? g_wvi_lo : g_wvl_lo;
    #pragma unroll
    for (int i = 0; i < 4; i++) {
        int idx = off + i * 256 + threadIdx.x;
        float2 v = ((const float2*)W)[idx];
        bf16 hx = __float2bfloat16_rn(v.x), hy = __float2bfloat16_rn(v.y);
        bf16 lx = __float2bfloat16_rn(v.x - __bfloat162float(hx));
        bf16 ly = __float2bfloat16_rn(v.y - __bfloat162float(hy));
        ((u32*)hi)[idx] = (u32)__bfloat16_as_ushort(hx) | ((u32)__bfloat16_as_ushort(hy) << 16);
        ((u32*)lo)[idx] = (u32)__bfloat16_as_ushort(lx) | ((u32)__bfloat16_as_ushort(ly) << 16);
    }
}

// ================= GEMM machinery (R15, unchanged) =================
#define LS 40
#define NCHN 64

template<int BN, bool BTRANS>
__device__ __forceinline__
void load_tile(bf16* As, bf16* Bs, int c,
               const bf16* Ahi, const bf16* Alo, int lda, int bm,
               const bf16* Bhi, const bf16* Blo, int ldb, int bn, int t)
{
    const bool hip = c < 32;
    const int kb = (c & 31) * 32;
    const bf16* Ap = hip ? Ahi : Alo;
    {
        int row = t >> 1, ch = (t & 1) * 2;
        const bf16* src = Ap + (long)(bm + row) * lda + kb + ch * 8;
        u32 dst = smem_u32(&As[row*LS + ch*8]);
        CPA(dst, src); CPA(dst + 16, src + 8);
    }
    if (!BTRANS) {
        int row = t >> 2, ch = t & 3;
        const bf16* s0 = Bhi + (long)(bn + row) * ldb + kb + ch * 8;
        CPA(smem_u32(&Bs[row*LS + ch*8]), s0);
        if (hip) {
            const bf16* s1 = Blo + (long)(bn + row) * ldb + kb + ch * 8;
            CPA(smem_u32(&Bs[BN*LS + row*LS + ch*8]), s1);
        }
    } else {
        int mrow = t >> 3, nc0 = (t & 7) * 16;
        {
            const bf16* s0 = Bhi + (long)(kb + mrow) * ldb + bn + nc0;
            bf16 tmp[16];
            *(uint4*)tmp = *(const uint4*)s0;
            *(uint4*)(tmp + 8) = *(const uint4*)(s0 + 8);
            #pragma unroll
            for (int j = 0; j < 16; j++) Bs[(nc0 + j)*LS + mrow] = tmp[j];
        }
        if (hip) {
            const bf16* s1 = Blo + (long)(kb + mrow) * ldb + bn + nc0;
            bf16 tmp[16];
            *(uint4*)tmp = *(const uint4*)s1;
            *(uint4*)(tmp + 8) = *(const uint4*)(s1 + 8);
            #pragma unroll
            for (int j = 0; j < 16; j++) Bs[BN*LS + (nc0 + j)*LS + mrow] = tmp[j];
        }
    }
}

// B via ldmatrix.x4: two n-tiles per LDSM (verified R15)
template<int BN>
__device__ __forceinline__
void mma_part(const bf16* Bp, const u32 (&a)[2][4], float (&acc)[2][BN/16][4],
              int kk, int lane, int wn)
{
    constexpr int NTN = BN / 16;
    int g = lane >> 3;
    #pragma unroll
    for (int ntp = 0; ntp < NTN/2; ntp++) {
        u32 bd = smem_u32(&Bp[(wn*(BN/2) + ntp*16 + ((g & 1) << 3) + (lane & 7))*LS
                              + kk + ((g >> 1) << 3)]);
        u32 r0, r1, r2, r3;
        asm volatile("ldmatrix.sync.aligned.m8n8.x4.shared.b16 {%0,%1,%2,%3}, [%4];"
            : "=r"(r0), "=r"(r1), "=r"(r2), "=r"(r3) : "r"(bd));
        #pragma unroll
        for (int mt = 0; mt < 2; mt++) {
            asm volatile(
                "mma.sync.aligned.m16n8k16.row.col.f32.bf16.bf16.f32 "
                "{%0,%1,%2,%3}, {%4,%5,%6,%7}, {%8,%9}, {%0,%1,%2,%3};"
                : "+f"(acc[mt][2*ntp][0]), "+f"(acc[mt][2*ntp][1]),
                  "+f"(acc[mt][2*ntp][2]), "+f"(acc[mt][2*ntp][3])
                : "r"(a[mt][0]), "r"(a[mt][1]), "r"(a[mt][2]), "r"(a[mt][3]),
                  "r"(r0), "r"(r2));
            asm volatile(
                "mma.sync.aligned.m16n8k16.row.col.f32.bf16.bf16.f32 "
                "{%0,%1,%2,%3}, {%4,%5,%6,%7}, {%8,%9}, {%0,%1,%2,%3};"
                : "+f"(acc[mt][2*ntp+1][0]), "+f"(acc[mt][2*ntp+1][1]),
                  "+f"(acc[mt][2*ntp+1][2]), "+f"(acc[mt][2*ntp+1][3])
                : "r"(a[mt][0]), "r"(a[mt][1]), "r"(a[mt][2]), "r"(a[mt][3]),
                  "r"(r1), "r"(r3));
        }
    }
}

template<int BN>
__device__ __forceinline__
void compute_tile(const bf16* As, const bf16* Bs, float (&acc)[2][BN/16][4],
                  int t, bool hip)
{
    int lane = t & 31, wid = t >> 5;
    int wm = wid & 3, wn = wid >> 2;
    #pragma unroll
    for (int kk = 0; kk < 32; kk += 16) {
        u32 a[2][4];
        #pragma unroll
        for (int mt = 0; mt < 2; mt++) {
            u32 ad = smem_u32(&As[(wm*32 + mt*16 + (lane & 15))*LS + kk + ((lane >> 4) << 3)]);
            asm volatile("ldmatrix.sync.aligned.m8n8.x4.shared.b16 {%0,%1,%2,%3}, [%4];"
                : "=r"(a[mt][0]), "=r"(a[mt][1]), "=r"(a[mt][2]), "=r"(a[mt][3]) : "r"(ad));
        }
        mma_part<BN>(Bs, a, acc, kk, lane, wn);
        if (hip) mma_part<BN>(Bs + BN*LS, a, acc, kk, lane, wn);
    }
}

template<int BN, bool BTRANS, bool SPLIT, int NS>
__device__ void mma_gemm_body(char* smem,
    const bf16* Ahi, const bf16* Alo, int lda,
    const bf16* Bhi, const bf16* Blo, int ldb,
    float* Cf, bf16* Chi, bf16* Clo, int ldc,
    const float* bias, int bm, int bn)
{
    constexpr int NTN = BN / 16;
    constexpr int ASTG = 128 * LS;
    constexpr int BSTG = 2 * BN * LS;
    bf16* Asg = (bf16*)smem;
    bf16* Bsg = (bf16*)(smem + NS * ASTG * 2);
    const int t = threadIdx.x;
    float acc[2][NTN][4];
    #pragma unroll
    for (int i = 0; i < 2; i++)
        #pragma unroll
        for (int j = 0; j < NTN; j++)
            #pragma unroll
            for (int q = 0; q < 4; q++) acc[i][j][q] = 0.f;

    #pragma unroll
    for (int c = 0; c < NS - 1; c++) {
        load_tile<BN, BTRANS>(Asg + c*ASTG, Bsg + c*BSTG, c,
                              Ahi, Alo, lda, bm, Bhi, Blo, ldb, bn, t);
        CPC();
    }
    for (int c = 0; c < NCHN; c++) {
        int st = c % NS;
        CPW(NS - 2);
        __syncthreads();
        int cn = c + NS - 1;
        if (cn < NCHN) {
            load_tile<BN, BTRANS>(Asg + (cn % NS)*ASTG, Bsg + (cn % NS)*BSTG, cn,
                                  Ahi, Alo, lda, bm, Bhi, Blo, ldb, bn, t);
            CPC();
        }
        compute_tile<BN>(Asg + st*ASTG, Bsg + st*BSTG, acc, t, c < 32);
    }

    int lane = t & 31, wid = t >> 5, wm = wid & 3, wn = wid >> 2;
    int gr = lane >> 2, gc = (lane & 3) * 2;
    #pragma unroll
    for (int mt = 0; mt < 2; mt++) {
        #pragma unroll
        for (int nt = 0; nt < NTN; nt++) {
            int col = bn + wn*(BN/2) + nt*8 + gc;
            float b0 = bias ? bias[col]     : 0.f;
            float b1 = bias ? bias[col + 1] : 0.f;
            long r0 = bm + wm*32 + mt*16 + gr;
            long r1 = r0 + 8;
            float v00 = acc[mt][nt][0] + b0, v01 = acc[mt][nt][1] + b1;
            float v10 = acc[mt][nt][2] + b0, v11 = acc[mt][nt][3] + b1;
            if (SPLIT) {
                store_split(Chi, Clo, r0*ldc + col, v00, v01);
                store_split(Chi, Clo, r1*ldc + col, v10, v11);
            } else {
                *(float2*)&Cf[r0*ldc + col] = make_float2(v00, v01);
                *(float2*)&Cf[r1*ldc + col] = make_float2(v10, v11);
            }
        }
    }
}

template<int BN, bool SPLIT>
__global__ __launch_bounds__(256)
void mma_gemm(const bf16* Ahi, const bf16* Alo, int lda, long gsA,
              const bf16* Bhi, const bf16* Blo, long gsB,
              float* Cf, bf16* Chi, bf16* Clo, long gsC,
              const float* bias, long gsBias)
{
    extern __shared__ char smem[];
    long z = blockIdx.z;
    mma_gemm_body<BN, false, SPLIT, 3>(smem,
        Ahi + z*gsA, Alo + z*gsA, lda,
        Bhi + z*gsB, Blo + z*gsB, 1024,
        Cf  ? Cf  + z*gsC : (float*)0,
        Chi ? Chi + z*gsC : (bf16*)0,
        Clo ? Clo + z*gsC : (bf16*)0, 1024,
        bias ? bias + z*gsBias : (const float*)0,
        blockIdx.x * 128, blockIdx.y * BN);
}

// ================= fused scores + softmax + y (unchanged) ============
#define PX 1028
__device__ __forceinline__ void aggr_body(float* sm, const float* __restrict__ x, int sb)
{
    float* xs  = sm;
    float* att = sm + 16 * PX;

    const int t = threadIdx.x;
    const int s = sb >> 5, b = sb & 31;

    #pragma unroll
    for (int i = 0; i < 16; i++) {
        int f4 = i * 256 + t;
        int e = f4 >> 8, d4 = f4 & 255;
        float4 v = ((const float4*)x)[((long)((s*16 + e)*32 + b)) * 256 + d4];
        *(float4*)&xs[e*PX + d4*4] = v;
    }
    __syncthreads();

    {
        const int h = t >> 4, e = t & 15;
        const float4* xr = (const float4*)&xs[e*PX];
        const float4* qr = (const float4*)&g_qk[h*D_];
        float acc = 0.f;
        #pragma unroll 8
        for (int i = 0; i < 256; i++) {
            float4 a = xr[i], q = qr[i];
            acc += a.x*q.x + a.y*q.y + a.z*q.z + a.w*q.w;
        }
        float mx = acc;
        #pragma unroll
        for (int o = 8; o; o >>= 1) mx = fmaxf(mx, __shfl_xor_sync(0xffffffffu, mx, o, 16));
        float p = __expf(acc - mx);
        float sum = p;
        #pragma unroll
        for (int o = 8; o; o >>= 1) sum += __shfl_xor_sync(0xffffffffu, sum, o, 16);
        att[t] = p / sum;
    }
    __syncthreads();

    float4 acch[16];
    #pragma unroll
    for (int h = 0; h < 16; h++) acch[h] = make_float4(0.f, 0.f, 0.f, 0.f);
    #pragma unroll
    for (int et = 0; et < 4; et++) {
        float4 xv[4];
        #pragma unroll
        for (int e2 = 0; e2 < 4; e2++)
            xv[e2] = *(const float4*)&xs[(et*4 + e2)*PX + t*4];
        #pragma unroll
        for (int h = 0; h < 16; h++) {
            #pragma unroll
            for (int e2 = 0; e2 < 4; e2++) {
                float a = att[h*16 + et*4 + e2];
                acch[h].x = fmaf(a, xv[e2].x, acch[h].x);
                acch[h].y = fmaf(a, xv[e2].y, acch[h].y);
                acch[h].z = fmaf(a, xv[e2].z, acch[h].z);
                acch[h].w = fmaf(a, xv[e2].w, acch[h].w);
            }
        }
    }
    #pragma unroll
    for (int h = 0; h < 16; h++) {
        float4 v = acch[h];
        long base = ((long)sb*16 + h)*1024 + t*4;
        store_split(g_yhi, g_ylo, base,     v.x, v.y);
        store_split(g_yhi, g_ylo, base + 2, v.z, v.w);
    }
}

// fat: blocks [0,64) Wcv (mma, BTRANS, NS=2); rest aggr
#define WCV_BLOCKS 64
__global__ __launch_bounds__(256)
void k_fat(const float* __restrict__ x)
{
    extern __shared__ char sm[];
    if (blockIdx.x < WCV_BLOCKS) {
        int wb = blockIdx.x;
        mma_gemm_body<128, true, true, 2>(sm,
            g_wvi_hi, g_wvi_lo, 1024,
            g_wvl_hi, g_wvl_lo, 1024,
            (float*)0, g_wcv_hi, g_wcv_lo, 1024,
            (const float*)0,
            (wb >> 3) * 128, (wb & 7) * 128);
    } else {
        aggr_body((float*)sm, x, blockIdx.x - WCV_BLOCKS);
    }
}

// ================= launch =================
extern "C" void kernel_launch(void* const* d_in, const int* in_sizes, int n_in,
                              void* d_out, int out_size)
{
    const float* x = (const float*)d_in[0];
    int qi = n_in - 13;
    const float* query  = (const float*)d_in[qi + 0];
    const float* Wk_lin = (const float*)d_in[qi + 1];
    const float* Wv_lin = (const float*)d_in[qi + 3];
    const float* bv_lin = (const float*)d_in[qi + 4];
    const float* Wq_in  = (const float*)d_in[qi + 5];
    const float* bq_in  = (const float*)d_in[qi + 6];
    const float* Wk_in  = (const float*)d_in[qi + 7];
    const float* Wv_in  = (const float*)d_in[qi + 9];
    const float* bv_in  = (const float*)d_in[qi + 10];
    const float* Wo     = (const float*)d_in[qi + 11];
    const float* bo     = (const float*)d_in[qi + 12];
    float* out = (float*)d_out;

    float *p_bcv, *p_qk;
    bf16 *p_yhi, *p_ylo, *p_wcvh, *p_wcvl, *p_woh, *p_wol, *p_cth, *p_ctl;
    cudaGetSymbolAddress((void**)&p_bcv,  g_bcv);
    cudaGetSymbolAddress((void**)&p_qk,   g_qk);
    cudaGetSymbolAddress((void**)&p_yhi,  g_yhi);
    cudaGetSymbolAddress((void**)&p_ylo,  g_ylo);
    cudaGetSymbolAddress((void**)&p_wcvh, g_wcv_hi);
    cudaGetSymbolAddress((void**)&p_wcvl, g_wcv_lo);
    cudaGetSymbolAddress((void**)&p_woh,  g_wo_hi);
    cudaGetSymbolAddress((void**)&p_wol,  g_wo_lo);
    cudaGetSymbolAddress((void**)&p_cth,  g_ctx_hi);
    cudaGetSymbolAddress((void**)&p_ctl,  g_ctx_lo);

    const int FAT_SMEM = (16*PX + 256) * 4;
    const int CTX_SMEM = 3*128*LS*2 + 3*2*64*LS*2;   // 61440
    const int OUT_SMEM = CTX_SMEM;
    static int attr_set = 0;
    if (!attr_set) {
        cudaFuncSetAttribute(k_fat, cudaFuncAttributeMaxDynamicSharedMemorySize, FAT_SMEM);
        cudaFuncSetAttribute(mma_gemm<64, true>,
                             cudaFuncAttributeMaxDynamicSharedMemorySize, CTX_SMEM);
        cudaFuncSetAttribute(mma_gemm<64, false>,
                             cudaFuncAttributeMaxDynamicSharedMemorySize, OUT_SMEM);
        attr_set = 1;
    }

    // 0. zero qk accumulator
    cudaMemsetAsync(p_qk, 0, H_*D_*sizeof(float), 0);
    // 1. weight splits
    k_split3<<<1536, 256>>>(Wo, Wv_in, Wv_lin);
    // 2. qp + bcv
    k_row2<<<256, 256>>>(Wq_in, query, bq_in, Wv_in, bv_lin, bv_in);
    // 3. t = fold(qp, Wk_in)
    k_t<<<dim3(8, 16), 128>>>(Wk_in);
    // 4. qk = t @ Wk_lin  (256 CTAs, MLP=8)
    k_qk3<<<dim3(8, 32), 128>>>(Wk_lin);
    // 5. fat: Wcv mma (64 blocks) || scores+softmax+y (2048 blocks)
    k_fat<<<WCV_BLOCKS + SB_, 256, FAT_SMEM>>>(x);
    // 6. ctx_h = y_h @ Wcv_h^T + bcv_h   (NS=3)
    mma_gemm<64, true><<<dim3(16, 1, 16), 256, CTX_SMEM>>>(
        p_yhi, p_ylo, H_*D_, (long)D_,
        p_wcvh, p_wcvl, (long)64*D_,
        (float*)0, p_cth, p_ctl, (long)64,
        p_bcv, (long)64);
    // 7. out = ctx @ Wo^T + bo   (NS=3)
    mma_gemm<64, false><<<dim3(16, 16, 1), 256, OUT_SMEM>>>(
        p_cth, p_ctl, D_, 0,
        p_woh, p_wol, 0,
        out, (bf16*)0, (bf16*)0, 0,
        bo, 0);
}

// round 17
// speedup vs baseline: 1.7413x; 1.0250x over previous
#include <cuda_runtime.h>
#include <cuda_bf16.h>
#include <math.h>

#define S_  64
#define E_  16
#define B_  32
#define D_  1024
#define H_  16
#define SB_ (S_*B_)

typedef unsigned long long u64;
typedef unsigned int u32;
typedef __nv_bfloat16 bf16;

// ---------------- device scratch ----------------
__device__ float g_qp [D_];
__device__ float g_t  [H_*D_];
__device__ float g_qk [H_*D_];
__device__ float g_bcv[D_];
__device__ bf16 g_yhi[SB_*H_*D_];
__device__ bf16 g_ylo[SB_*H_*D_];
__device__ bf16 g_wvi_hi[D_*D_], g_wvi_lo[D_*D_];
__device__ bf16 g_wvl_hi[D_*D_], g_wvl_lo[D_*D_];
__device__ bf16 g_wcv_hi[D_*D_], g_wcv_lo[D_*D_];
__device__ bf16 g_wo_hi [D_*D_], g_wo_lo [D_*D_];
__device__ bf16 g_ctx_hi[SB_*D_], g_ctx_lo[SB_*D_];

// ---------------- helpers ----------------
__device__ __forceinline__ u32 smem_u32(const void* p) {
    u32 a; asm("{ .reg .u64 t; cvta.to.shared.u64 t, %1; cvt.u32.u64 %0, t; }"
               : "=r"(a) : "l"(p)); return a;
}
#define CPA(dst, src) \
    asm volatile("cp.async.cg.shared.global [%0], [%1], 16;" :: "r"(dst), "l"(src))
#define CPC() asm volatile("cp.async.commit_group;" ::: "memory")
#define CPW(n) asm volatile("cp.async.wait_group %0;" :: "n"(n) : "memory")

__device__ __forceinline__ u64 dup2(float a) {
    u64 r; asm("mov.b64 %0, {%1, %1};" : "=l"(r) : "f"(a)); return r;
}
__device__ __forceinline__ void ffma2(u64& c, u64 a, u64 b) {
    asm("fma.rn.f32x2 %0, %1, %2, %0;" : "+l"(c) : "l"(a), "l"(b));
}
__device__ __forceinline__ float2 unpk(u64 v) {
    float x, y; asm("mov.b64 {%0, %1}, %2;" : "=f"(x), "=f"(y) : "l"(v));
    return make_float2(x, y);
}

__device__ __forceinline__ void store_split(bf16* hi, bf16* lo, long idx,
                                            float v0, float v1) {
    bf16 h0 = __float2bfloat16_rn(v0), h1 = __float2bfloat16_rn(v1);
    bf16 l0 = __float2bfloat16_rn(v0 - __bfloat162float(h0));
    bf16 l1 = __float2bfloat16_rn(v1 - __bfloat162float(h1));
    *(u32*)&hi[idx] = (u32)__bfloat16_as_ushort(h0) | ((u32)__bfloat16_as_ushort(h1) << 16);
    *(u32*)&lo[idx] = (u32)__bfloat16_as_ushort(l0) | ((u32)__bfloat16_as_ushort(l1) << 16);
}

// ================= front-end (R16, unchanged) =================
__device__ __forceinline__
void rowdot_warp(const float* __restrict__ W, const float* __restrict__ v,
                 const float* __restrict__ bias, float* __restrict__ out,
                 int w, int lane, float scale)
{
    const float4* row4 = (const float4*)(W + (long)w * D_);
    const float4* v4   = (const float4*)v;
    float acc = 0.f;
    #pragma unroll 8
    for (int c = lane; c < D_/4; c += 32) {
        float4 a = row4[c], b = v4[c];
        acc += a.x*b.x + a.y*b.y + a.z*b.z + a.w*b.w;
    }
    #pragma unroll
    for (int o = 16; o; o >>= 1) acc += __shfl_xor_sync(0xffffffffu, acc, o);
    if (!lane) out[w] = (acc + bias[w]) * scale;
}

__global__ void k_row2(const float* __restrict__ Wq_in, const float* __restrict__ query,
                       const float* __restrict__ bq_in,
                       const float* __restrict__ Wv_in, const float* __restrict__ bv_lin,
                       const float* __restrict__ bv_in)
{
    int t = threadIdx.x;
    if (blockIdx.x < 128) {
        rowdot_warp(Wq_in, query, bq_in, g_qp,
                    blockIdx.x * 8 + (t >> 5), t & 31, 0.125f);
    } else {
        rowdot_warp(Wv_in, bv_lin, bv_in, g_bcv,
                    (blockIdx.x - 128) * 8 + (t >> 5), t & 31, 1.0f);
    }
}

__global__ __launch_bounds__(128)
void k_t(const float* __restrict__ Wk_in)
{
    int h = blockIdx.y;
    int m = blockIdx.x * 128 + threadIdx.x;
    float acc = 0.f;
    #pragma unroll 8
    for (int j = 0; j < 64; j++)
        acc += g_qp[h*64 + j] * Wk_in[(long)(h*64 + j) * D_ + m];
    g_t[h*D_ + m] = acc;
}

__global__ __launch_bounds__(128)
void k_qk3(const float* __restrict__ Wk_lin)
{
    __shared__ float ts[16 * 32];
    int d  = blockIdx.x * 128 + threadIdx.x;
    int m0 = blockIdx.y * 32;
    for (int i = threadIdx.x; i < 16 * 32; i += 128)
        ts[i] = g_t[(i >> 5) * D_ + m0 + (i & 31)];
    __syncthreads();
    float acc[16];
    #pragma unroll
    for (int h = 0; h < 16; h++) acc[h] = 0.f;
    #pragma unroll
    for (int mb = 0; mb < 32; mb += 8) {
        float w[8];
        #pragma unroll
        for (int u = 0; u < 8; u++)
            w[u] = Wk_lin[(long)(m0 + mb + u) * D_ + d];
        #pragma unroll
        for (int u = 0; u < 8; u++)
            #pragma unroll
            for (int h = 0; h < 16; h++)
                acc[h] += ts[h*32 + mb + u] * w[u];
    }
    #pragma unroll
    for (int h = 0; h < 16; h++) atomicAdd(&g_qk[h*D_ + d], acc[h]);
}

__global__ __launch_bounds__(256)
void k_split3(const float* __restrict__ W0, const float* __restrict__ W1,
              const float* __restrict__ W2)
{
    int blk = blockIdx.x;
    int m = blk >> 9;
    int off = (blk & 511) * 1024;
    const float* W = (m == 0) ? W0 : (m == 1) ? W1 : W2;
    bf16* hi = (m == 0) ? g_wo_hi : (m == 1) ? g_wvi_hi : g_wvl_hi;
    bf16* lo = (m == 0) ? g_wo_lo : (m == 1) ? g_wvi_lo : g_wvl_lo;
    #pragma unroll
    for (int i = 0; i < 4; i++) {
        int idx = off + i * 256 + threadIdx.x;
        float2 v = ((const float2*)W)[idx];
        bf16 hx = __float2bfloat16_rn(v.x), hy = __float2bfloat16_rn(v.y);
        bf16 lx = __float2bfloat16_rn(v.x - __bfloat162float(hx));
        bf16 ly = __float2bfloat16_rn(v.y - __bfloat162float(hy));
        ((u32*)hi)[idx] = (u32)__bfloat16_as_ushort(hx) | ((u32)__bfloat16_as_ushort(hy) << 16);
        ((u32*)lo)[idx] = (u32)__bfloat16_as_ushort(lx) | ((u32)__bfloat16_as_ushort(ly) << 16);
    }
}

// ================= GEMM machinery (R16, unchanged) =================
#define LS 40
#define NCHN 64

template<int BN, bool BTRANS>
__device__ __forceinline__
void load_tile(bf16* As, bf16* Bs, int c,
               const bf16* Ahi, const bf16* Alo, int lda, int bm,
               const bf16* Bhi, const bf16* Blo, int ldb, int bn, int t)
{
    const bool hip = c < 32;
    const int kb = (c & 31) * 32;
    const bf16* Ap = hip ? Ahi : Alo;
    {
        int row = t >> 1, ch = (t & 1) * 2;
        const bf16* src = Ap + (long)(bm + row) * lda + kb + ch * 8;
        u32 dst = smem_u32(&As[row*LS + ch*8]);
        CPA(dst, src); CPA(dst + 16, src + 8);
    }
    if (!BTRANS) {
        int row = t >> 2, ch = t & 3;
        const bf16* s0 = Bhi + (long)(bn + row) * ldb + kb + ch * 8;
        CPA(smem_u32(&Bs[row*LS + ch*8]), s0);
        if (hip) {
            const bf16* s1 = Blo + (long)(bn + row) * ldb + kb + ch * 8;
            CPA(smem_u32(&Bs[BN*LS + row*LS + ch*8]), s1);
        }
    } else {
        int mrow = t >> 3, nc0 = (t & 7) * 16;
        {
            const bf16* s0 = Bhi + (long)(kb + mrow) * ldb + bn + nc0;
            bf16 tmp[16];
            *(uint4*)tmp = *(const uint4*)s0;
            *(uint4*)(tmp + 8) = *(const uint4*)(s0 + 8);
            #pragma unroll
            for (int j = 0; j < 16; j++) Bs[(nc0 + j)*LS + mrow] = tmp[j];
        }
        if (hip) {
            const bf16* s1 = Blo + (long)(kb + mrow) * ldb + bn + nc0;
            bf16 tmp[16];
            *(uint4*)tmp = *(const uint4*)s1;
            *(uint4*)(tmp + 8) = *(const uint4*)(s1 + 8);
            #pragma unroll
            for (int j = 0; j < 16; j++) Bs[BN*LS + (nc0 + j)*LS + mrow] = tmp[j];
        }
    }
}

template<int BN>
__device__ __forceinline__
void mma_part(const bf16* Bp, const u32 (&a)[2][4], float (&acc)[2][BN/16][4],
              int kk, int lane, int wn)
{
    constexpr int NTN = BN / 16;
    int g = lane >> 3;
    #pragma unroll
    for (int ntp = 0; ntp < NTN/2; ntp++) {
        u32 bd = smem_u32(&Bp[(wn*(BN/2) + ntp*16 + ((g & 1) << 3) + (lane & 7))*LS
                              + kk + ((g >> 1) << 3)]);
        u32 r0, r1, r2, r3;
        asm volatile("ldmatrix.sync.aligned.m8n8.x4.shared.b16 {%0,%1,%2,%3}, [%4];"
            : "=r"(r0), "=r"(r1), "=r"(r2), "=r"(r3) : "r"(bd));
        #pragma unroll
        for (int mt = 0; mt < 2; mt++) {
            asm volatile(
                "mma.sync.aligned.m16n8k16.row.col.f32.bf16.bf16.f32 "
                "{%0,%1,%2,%3}, {%4,%5,%6,%7}, {%8,%9}, {%0,%1,%2,%3};"
                : "+f"(acc[mt][2*ntp][0]), "+f"(acc[mt][2*ntp][1]),
                  "+f"(acc[mt][2*ntp][2]), "+f"(acc[mt][2*ntp][3])
                : "r"(a[mt][0]), "r"(a[mt][1]), "r"(a[mt][2]), "r"(a[mt][3]),
                  "r"(r0), "r"(r2));
            asm volatile(
                "mma.sync.aligned.m16n8k16.row.col.f32.bf16.bf16.f32 "
                "{%0,%1,%2,%3}, {%4,%5,%6,%7}, {%8,%9}, {%0,%1,%2,%3};"
                : "+f"(acc[mt][2*ntp+1][0]), "+f"(acc[mt][2*ntp+1][1]),
                  "+f"(acc[mt][2*ntp+1][2]), "+f"(acc[mt][2*ntp+1][3])
                : "r"(a[mt][0]), "r"(a[mt][1]), "r"(a[mt][2]), "r"(a[mt][3]),
                  "r"(r1), "r"(r3));
        }
    }
}

template<int BN>
__device__ __forceinline__
void compute_tile(const bf16* As, const bf16* Bs, float (&acc)[2][BN/16][4],
                  int t, bool hip)
{
    int lane = t & 31, wid = t >> 5;
    int wm = wid & 3, wn = wid >> 2;
    #pragma unroll
    for (int kk = 0; kk < 32; kk += 16) {
        u32 a[2][4];
        #pragma unroll
        for (int mt = 0; mt < 2; mt++) {
            u32 ad = smem_u32(&As[(wm*32 + mt*16 + (lane & 15))*LS + kk + ((lane >> 4) << 3)]);
            asm volatile("ldmatrix.sync.aligned.m8n8.x4.shared.b16 {%0,%1,%2,%3}, [%4];"
                : "=r"(a[mt][0]), "=r"(a[mt][1]), "=r"(a[mt][2]), "=r"(a[mt][3]) : "r"(ad));
        }
        mma_part<BN>(Bs, a, acc, kk, lane, wn);
        if (hip) mma_part<BN>(Bs + BN*LS, a, acc, kk, lane, wn);
    }
}

template<int BN, bool BTRANS, bool SPLIT, int NS>
__device__ void mma_gemm_body(char* smem,
    const bf16* Ahi, const bf16* Alo, int lda,
    const bf16* Bhi, const bf16* Blo, int ldb,
    float* Cf, bf16* Chi, bf16* Clo, int ldc,
    const float* bias, int bm, int bn)
{
    constexpr int NTN = BN / 16;
    constexpr int ASTG = 128 * LS;
    constexpr int BSTG = 2 * BN * LS;
    bf16* Asg = (bf16*)smem;
    bf16* Bsg = (bf16*)(smem + NS * ASTG * 2);
    const int t = threadIdx.x;
    float acc[2][NTN][4];
    #pragma unroll
    for (int i = 0; i < 2; i++)
        #pragma unroll
        for (int j = 0; j < NTN; j++)
            #pragma unroll
            for (int q = 0; q < 4; q++) acc[i][j][q] = 0.f;

    #pragma unroll
    for (int c = 0; c < NS - 1; c++) {
        load_tile<BN, BTRANS>(Asg + c*ASTG, Bsg + c*BSTG, c,
                              Ahi, Alo, lda, bm, Bhi, Blo, ldb, bn, t);
        CPC();
    }
    for (int c = 0; c < NCHN; c++) {
        int st = c % NS;
        CPW(NS - 2);
        __syncthreads();
        int cn = c + NS - 1;
        if (cn < NCHN) {
            load_tile<BN, BTRANS>(Asg + (cn % NS)*ASTG, Bsg + (cn % NS)*BSTG, cn,
                                  Ahi, Alo, lda, bm, Bhi, Blo, ldb, bn, t);
            CPC();
        }
        compute_tile<BN>(Asg + st*ASTG, Bsg + st*BSTG, acc, t, c < 32);
    }

    int lane = t & 31, wid = t >> 5, wm = wid & 3, wn = wid >> 2;
    int gr = lane >> 2, gc = (lane & 3) * 2;
    #pragma unroll
    for (int mt = 0; mt < 2; mt++) {
        #pragma unroll
        for (int nt = 0; nt < NTN; nt++) {
            int col = bn + wn*(BN/2) + nt*8 + gc;
            float b0 = bias ? bias[col]     : 0.f;
            float b1 = bias ? bias[col + 1] : 0.f;
            long r0 = bm + wm*32 + mt*16 + gr;
            long r1 = r0 + 8;
            float v00 = acc[mt][nt][0] + b0, v01 = acc[mt][nt][1] + b1;
            float v10 = acc[mt][nt][2] + b0, v11 = acc[mt][nt][3] + b1;
            if (SPLIT) {
                store_split(Chi, Clo, r0*ldc + col, v00, v01);
                store_split(Chi, Clo, r1*ldc + col, v10, v11);
            } else {
                *(float2*)&Cf[r0*ldc + col] = make_float2(v00, v01);
                *(float2*)&Cf[r1*ldc + col] = make_float2(v10, v11);
            }
        }
    }
}

template<int BN, bool SPLIT>
__global__ __launch_bounds__(256)
void mma_gemm(const bf16* Ahi, const bf16* Alo, int lda, long gsA,
              const bf16* Bhi, const bf16* Blo, long gsB,
              float* Cf, bf16* Chi, bf16* Clo, long gsC,
              const float* bias, long gsBias)
{
    extern __shared__ char smem[];
    long z = blockIdx.z;
    mma_gemm_body<BN, false, SPLIT, 3>(smem,
        Ahi + z*gsA, Alo + z*gsA, lda,
        Bhi + z*gsB, Blo + z*gsB, 1024,
        Cf  ? Cf  + z*gsC : (float*)0,
        Chi ? Chi + z*gsC : (bf16*)0,
        Clo ? Clo + z*gsC : (bf16*)0, 1024,
        bias ? bias + z*gsBias : (const float*)0,
        blockIdx.x * 128, blockIdx.y * BN);
}

// ================= fused scores + softmax + y (f32x2 FMA) ============
#define PX 1028
__device__ __forceinline__ void aggr_body(float* sm, const float* __restrict__ x, int sb)
{
    float* xs  = sm;
    float* att = sm + 16 * PX;

    const int t = threadIdx.x;
    const int s = sb >> 5, b = sb & 31;

    #pragma unroll
    for (int i = 0; i < 16; i++) {
        int f4 = i * 256 + t;
        int e = f4 >> 8, d4 = f4 & 255;
        float4 v = ((const float4*)x)[((long)((s*16 + e)*32 + b)) * 256 + d4];
        *(float4*)&xs[e*PX + d4*4] = v;
    }
    __syncthreads();

    { // score + softmax: thread t -> (h = t/16, e = t%16), f32x2 dot
        const int h = t >> 4, e = t & 15;
        const ulonglong2* xr = (const ulonglong2*)&xs[e*PX];      // e*4112 B, 16B-aligned
        const ulonglong2* qr = (const ulonglong2*)&g_qk[h*D_];
        u64 acc2 = 0ull;
        #pragma unroll 8
        for (int i = 0; i < 256; i++) {
            ulonglong2 a = xr[i], q = qr[i];
            ffma2(acc2, a.x, q.x);
            ffma2(acc2, a.y, q.y);
        }
        float2 pp = unpk(acc2);
        float acc = pp.x + pp.y;
        float mx = acc;
        #pragma unroll
        for (int o = 8; o; o >>= 1) mx = fmaxf(mx, __shfl_xor_sync(0xffffffffu, mx, o, 16));
        float p = __expf(acc - mx);
        float sum = p;
        #pragma unroll
        for (int o = 8; o; o >>= 1) sum += __shfl_xor_sync(0xffffffffu, sum, o, 16);
        att[t] = p / sum;
    }
    __syncthreads();

    // y: f32x2 accumulators (2 pairs per head = float4)
    u64 acch[16][2];
    #pragma unroll
    for (int h = 0; h < 16; h++) { acch[h][0] = 0ull; acch[h][1] = 0ull; }
    #pragma unroll
    for (int et = 0; et < 4; et++) {
        ulonglong2 xv[4];
        #pragma unroll
        for (int e2 = 0; e2 < 4; e2++)
            xv[e2] = *(const ulonglong2*)&xs[(et*4 + e2)*PX + t*4];
        #pragma unroll
        for (int h = 0; h < 16; h++) {
            #pragma unroll
            for (int e2 = 0; e2 < 4; e2++) {
                u64 ad = dup2(att[h*16 + et*4 + e2]);
                ffma2(acch[h][0], ad, xv[e2].x);
                ffma2(acch[h][1], ad, xv[e2].y);
            }
        }
    }
    #pragma unroll
    for (int h = 0; h < 16; h++) {
        float2 v01 = unpk(acch[h][0]);
        float2 v23 = unpk(acch[h][1]);
        long base = ((long)sb*16 + h)*1024 + t*4;
        store_split(g_yhi, g_ylo, base,     v01.x, v01.y);
        store_split(g_yhi, g_ylo, base + 2, v23.x, v23.y);
    }
}

// fat: blocks [0,64) Wcv (mma, BTRANS, NS=2); rest aggr
#define WCV_BLOCKS 64
__global__ __launch_bounds__(256)
void k_fat(const float* __restrict__ x)
{
    extern __shared__ char sm[];
    if (blockIdx.x < WCV_BLOCKS) {
        int wb = blockIdx.x;
        mma_gemm_body<128, true, true, 2>(sm,
            g_wvi_hi, g_wvi_lo, 1024,
            g_wvl_hi, g_wvl_lo, 1024,
            (float*)0, g_wcv_hi, g_wcv_lo, 1024,
            (const float*)0,
            (wb >> 3) * 128, (wb & 7) * 128);
    } else {
        aggr_body((float*)sm, x, blockIdx.x - WCV_BLOCKS);
    }
}

// ================= launch =================
extern "C" void kernel_launch(void* const* d_in, const int* in_sizes, int n_in,
                              void* d_out, int out_size)
{
    const float* x = (const float*)d_in[0];
    int qi = n_in - 13;
    const float* query  = (const float*)d_in[qi + 0];
    const float* Wk_lin = (const float*)d_in[qi + 1];
    const float* Wv_lin = (const float*)d_in[qi + 3];
    const float* bv_lin = (const float*)d_in[qi + 4];
    const float* Wq_in  = (const float*)d_in[qi + 5];
    const float* bq_in  = (const float*)d_in[qi + 6];
    const float* Wk_in  = (const float*)d_in[qi + 7];
    const float* Wv_in  = (const float*)d_in[qi + 9];
    const float* bv_in  = (const float*)d_in[qi + 10];
    const float* Wo     = (const float*)d_in[qi + 11];
    const float* bo     = (const float*)d_in[qi + 12];
    float* out = (float*)d_out;

    float *p_bcv, *p_qk;
    bf16 *p_yhi, *p_ylo, *p_wcvh, *p_wcvl, *p_woh, *p_wol, *p_cth, *p_ctl;
    cudaGetSymbolAddress((void**)&p_bcv,  g_bcv);
    cudaGetSymbolAddress((void**)&p_qk,   g_qk);
    cudaGetSymbolAddress((void**)&p_yhi,  g_yhi);
    cudaGetSymbolAddress((void**)&p_ylo,  g_ylo);
    cudaGetSymbolAddress((void**)&p_wcvh, g_wcv_hi);
    cudaGetSymbolAddress((void**)&p_wcvl, g_wcv_lo);
    cudaGetSymbolAddress((void**)&p_woh,  g_wo_hi);
    cudaGetSymbolAddress((void**)&p_wol,  g_wo_lo);
    cudaGetSymbolAddress((void**)&p_cth,  g_ctx_hi);
    cudaGetSymbolAddress((void**)&p_ctl,  g_ctx_lo);

    const int FAT_SMEM = (16*PX + 256) * 4;
    const int CTX_SMEM = 3*128*LS*2 + 3*2*64*LS*2;   // 61440
    const int OUT_SMEM = CTX_SMEM;
    static int attr_set = 0;
    if (!attr_set) {
        cudaFuncSetAttribute(k_fat, cudaFuncAttributeMaxDynamicSharedMemorySize, FAT_SMEM);
        cudaFuncSetAttribute(mma_gemm<64, true>,
                             cudaFuncAttributeMaxDynamicSharedMemorySize, CTX_SMEM);
        cudaFuncSetAttribute(mma_gemm<64, false>,
                             cudaFuncAttributeMaxDynamicSharedMemorySize, OUT_SMEM);
        attr_set = 1;
    }

    // 0. zero qk accumulator
    cudaMemsetAsync(p_qk, 0, H_*D_*sizeof(float), 0);
    // 1. weight splits
    k_split3<<<1536, 256>>>(Wo, Wv_in, Wv_lin);
    // 2. qp + bcv
    k_row2<<<256, 256>>>(Wq_in, query, bq_in, Wv_in, bv_lin, bv_in);
    // 3. t = fold(qp, Wk_in)
    k_t<<<dim3(8, 16), 128>>>(Wk_in);
    // 4. qk = t @ Wk_lin
    k_qk3<<<dim3(8, 32), 128>>>(Wk_lin);
    // 5. fat: Wcv mma (64 blocks) || scores+softmax+y (2048 blocks)
    k_fat<<<WCV_BLOCKS + SB_, 256, FAT_SMEM>>>(x);
    // 6. ctx_h = y_h @ Wcv_h^T + bcv_h   (NS=3)
    mma_gemm<64, true><<<dim3(16, 1, 16), 256, CTX_SMEM>>>(
        p_yhi, p_ylo, H_*D_, (long)D_,
        p_wcvh, p_wcvl, (long)64*D_,
        (float*)0, p_cth, p_ctl, (long)64,
        p_bcv, (long)64);
    // 7. out = ctx @ Wo^T + bo   (NS=3)
    mma_gemm<64, false><<<dim3(16, 16, 1), 256, OUT_SMEM>>>(
        p_cth, p_ctl, D_, 0,
        p_woh, p_wol, 0,
        out, (bf16*)0, (bf16*)0, 0,
        bo, 0);
}